// round 12
// baseline (speedup 1.0000x reference)
#include <cuda_runtime.h>
#include <cuda.h>
#include <cuda_bf16.h>
#include <cuda_fp16.h>
#include <cstdint>
#include <cstddef>
#include <dlfcn.h>

#define DINL __device__ __forceinline__

#define B_ROWS 8192
#define D_IN   12288
#define HID    2048
#define NCAP   96
#define CCH    2048

// ---- fallback (cp.async) GEMM tiling ----
#define TMT 128
#define TNT 128
#define TKT 64
#define SROW 72
#define TILE_BYTES (128 * SROW * 2)
#define STAGE_BYTES (4 * TILE_BYTES)
#define NSTAGE 3
#define SMEM_DYN (NSTAGE * STAGE_BYTES)

// ---- TMA GEMM tiling ----
#define TTILE 16384                       // 128 rows x 128 B
#define TSMEM (3 * 65536 + 1024)

// ---- scratch ----
static __device__ __nv_bfloat16 g_Xh [(size_t)B_ROWS * D_IN];
static __device__ __nv_bfloat16 g_Xl [(size_t)B_ROWS * D_IN];
static __device__ __nv_bfloat16 g_W1h[(size_t)HID * D_IN];
static __device__ __nv_bfloat16 g_W1l[(size_t)HID * D_IN];
static __device__ __nv_bfloat16 g_W2h[(size_t)HID * HID];
static __device__ __nv_bfloat16 g_W2l[(size_t)HID * HID];
static __device__ __half        g_W3t [(size_t)D_IN * HID];   // W3^T fp16 (TMA path)
static __device__ __half        g_W3f [(size_t)HID * D_IN];   // W3 fp16 (fallback)
static __device__ __nv_bfloat16 g_H1h[(size_t)B_ROWS * HID];
static __device__ __nv_bfloat16 g_H1l[(size_t)B_ROWS * HID];
static __device__ float         g_H2 [(size_t)B_ROWS * HID];
static __device__ __half        g_H2s[(size_t)B_ROWS * HID];  // dense sparsified fp16
static __device__ float         g_sv [(size_t)B_ROWS * NCAP];
static __device__ int           g_si [(size_t)B_ROWS * NCAP];
static __device__ int           g_sc [B_ROWS];

// ---- helpers ----
DINL uint32_t smem_u32(const void* p) {
    uint32_t a;
    asm("{ .reg .u64 t; cvta.to.shared.u64 t, %1; cvt.u32.u64 %0, t; }" : "=r"(a) : "l"(p));
    return a;
}
DINL bool elect_one() {
    uint32_t p;
    asm volatile("{ .reg .pred p; elect.sync _|p, 0xFFFFFFFF; selp.b32 %0, 1, 0, p; }" : "=r"(p));
    return p != 0;
}
DINL void cp16(uint32_t d, const void* s) {
    asm volatile("cp.async.cg.shared.global [%0], [%1], 16;" :: "r"(d), "l"(s));
}
DINL void cp_commit() { asm volatile("cp.async.commit_group;" ::: "memory"); }
template <int N> DINL void cp_wait() {
    asm volatile("cp.async.wait_group %0;" :: "n"(N) : "memory");
}
DINL void ldsm4(uint32_t& r0, uint32_t& r1, uint32_t& r2, uint32_t& r3, uint32_t addr) {
    asm volatile("ldmatrix.sync.aligned.m8n8.x4.shared.b16 {%0,%1,%2,%3}, [%4];"
                 : "=r"(r0), "=r"(r1), "=r"(r2), "=r"(r3) : "r"(addr));
}
DINL void mma_bf16(float* c, uint32_t a0, uint32_t a1, uint32_t a2, uint32_t a3,
                   uint32_t b0, uint32_t b1) {
    asm volatile(
        "mma.sync.aligned.m16n8k16.row.col.f32.bf16.bf16.f32 "
        "{%0,%1,%2,%3},{%4,%5,%6,%7},{%8,%9},{%0,%1,%2,%3};"
        : "+f"(c[0]), "+f"(c[1]), "+f"(c[2]), "+f"(c[3])
        : "r"(a0), "r"(a1), "r"(a2), "r"(a3), "r"(b0), "r"(b1));
}
DINL void mma_fp16(float* c, uint32_t a0, uint32_t a1, uint32_t a2, uint32_t a3,
                   uint32_t b0, uint32_t b1) {
    asm volatile(
        "mma.sync.aligned.m16n8k16.row.col.f32.f16.f16.f32 "
        "{%0,%1,%2,%3},{%4,%5,%6,%7},{%8,%9},{%0,%1,%2,%3};"
        : "+f"(c[0]), "+f"(c[1]), "+f"(c[2]), "+f"(c[3])
        : "r"(a0), "r"(a1), "r"(a2), "r"(a3), "r"(b0), "r"(b1));
}
DINL uint32_t pack_bf2(__nv_bfloat16 a, __nv_bfloat16 b) {
    return (uint32_t)__bfloat16_as_ushort(a) | ((uint32_t)__bfloat16_as_ushort(b) << 16);
}
DINL void mbar_init(uint32_t a, uint32_t c) {
    asm volatile("mbarrier.init.shared.b64 [%0], %1;" :: "r"(a), "r"(c) : "memory");
}
DINL void mbar_arrive(uint32_t a) {
    asm volatile("mbarrier.arrive.shared.b64 _, [%0];" :: "r"(a) : "memory");
}
DINL void mbar_expect(uint32_t a, uint32_t bytes) {
    asm volatile("mbarrier.arrive.expect_tx.shared.b64 _, [%0], %1;"
                 :: "r"(a), "r"(bytes) : "memory");
}
DINL void mbar_wait(uint32_t a, uint32_t par) {
    asm volatile(
        "{\n\t.reg .pred P;\n\t"
        "WL%=:\n\t"
        "mbarrier.try_wait.parity.acquire.cta.shared::cta.b64 P, [%0], %1, 0x989680;\n\t"
        "@P bra WD%=;\n\t"
        "bra WL%=;\n\t"
        "WD%=:\n\t}"
        :: "r"(a), "r"(par) : "memory");
}
DINL void tma2d(uint32_t dst, const void* map, int cx, int cy, uint32_t mbar) {
    asm volatile(
        "cp.async.bulk.tensor.2d.shared::cta.global.tile.mbarrier::complete_tx::bytes "
        "[%0], [%1, {%2, %3}], [%4];"
        :: "r"(dst), "l"(map), "r"(cx), "r"(cy), "r"(mbar) : "memory");
}

// ---- split X ----
__global__ void __launch_bounds__(256) split_kernel(
    const float4* __restrict__ src, uint2* __restrict__ dh, uint2* __restrict__ dl, size_t n4)
{
    size_t i = (size_t)blockIdx.x * 256u + threadIdx.x;
    if (i >= n4) return;
    float4 x = src[i];
    __nv_bfloat16 h0 = __float2bfloat16(x.x), h1 = __float2bfloat16(x.y);
    __nv_bfloat16 h2 = __float2bfloat16(x.z), h3 = __float2bfloat16(x.w);
    dh[i] = make_uint2(pack_bf2(h0, h1), pack_bf2(h2, h3));
    dl[i] = make_uint2(
        pack_bf2(__float2bfloat16(x.x - __bfloat162float(h0)),
                 __float2bfloat16(x.y - __bfloat162float(h1))),
        pack_bf2(__float2bfloat16(x.z - __bfloat162float(h2)),
                 __float2bfloat16(x.w - __bfloat162float(h3))));
}

// ---- transpose + split weights (bf16 pair) ----
__global__ void __launch_bounds__(256) tsplit_kernel(
    const float* __restrict__ src, __nv_bfloat16* __restrict__ dh,
    __nv_bfloat16* __restrict__ dl, int R, int C)
{
    __shared__ float tile[32][33];
    int c0 = blockIdx.x * 32, r0 = blockIdx.y * 32;
    int tx = threadIdx.x, ty = threadIdx.y;
#pragma unroll
    for (int j = 0; j < 32; j += 8)
        tile[ty + j][tx] = src[(size_t)(r0 + ty + j) * C + (c0 + tx)];
    __syncthreads();
#pragma unroll
    for (int j = 0; j < 32; j += 8) {
        float v = tile[tx][ty + j];
        size_t o = (size_t)(c0 + ty + j) * R + (r0 + tx);
        __nv_bfloat16 h = __float2bfloat16(v);
        dh[o] = h;
        dl[o] = __float2bfloat16(v - __bfloat162float(h));
    }
}

// ---- transpose W3 -> fp16 [C, R] ----
__global__ void __launch_bounds__(256) ttrans_h_kernel(
    const float* __restrict__ src, __half* __restrict__ dst, int R, int C)
{
    __shared__ float tile[32][33];
    int c0 = blockIdx.x * 32, r0 = blockIdx.y * 32;
    int tx = threadIdx.x, ty = threadIdx.y;
#pragma unroll
    for (int j = 0; j < 32; j += 8)
        tile[ty + j][tx] = src[(size_t)(r0 + ty + j) * C + (c0 + tx)];
    __syncthreads();
#pragma unroll
    for (int j = 0; j < 32; j += 8)
        dst[(size_t)(c0 + ty + j) * R + (r0 + tx)] = __float2half(tile[tx][ty + j]);
}

// ---- W3 f32 -> fp16 (fallback path) ----
__global__ void __launch_bounds__(256) htrunc_kernel(
    const float4* __restrict__ src, uint2* __restrict__ dst, size_t n4)
{
    size_t i = (size_t)blockIdx.x * 256u + threadIdx.x;
    if (i >= n4) return;
    float4 x = src[i];
    __half2 lo = __floats2half2_rn(x.x, x.y);
    __half2 hi = __floats2half2_rn(x.z, x.w);
    dst[i] = make_uint2(*(uint32_t*)&lo, *(uint32_t*)&hi);
}

// ---- exact top-k: dense fp16 sparsified out + compaction (fallback) ----
DINL unsigned fmap(float x) {
    unsigned b = __float_as_uint(x);
    return (b & 0x80000000u) ? ~b : (b | 0x80000000u);
}
__global__ void __launch_bounds__(256) topk_kernel(
    const float* __restrict__ H2, const int* __restrict__ knb,
    __half* __restrict__ hd,
    float* __restrict__ gv, int* __restrict__ gi, int* __restrict__ gc)
{
    __shared__ int hist[256];
    __shared__ unsigned sh_pref;
    __shared__ int sh_k;
    __shared__ float s_val[NCAP];
    __shared__ int s_idx[NCAP];
    __shared__ int wsum[8];
    __shared__ int s_tot;
    const int row = blockIdx.x, t = threadIdx.x;
    const int lane = t & 31, w = t >> 5;
    const float* rp = H2 + (size_t)row * HID;
    float v[8]; unsigned u[8];
#pragma unroll
    for (int j = 0; j < 8; j++) { v[j] = rp[t + 256 * j]; u[j] = fmap(v[j]); }
    int k = *knb;
    unsigned prefix = 0, mask = 0;
#pragma unroll 1
    for (int by = 3; by >= 0; by--) {
        hist[t] = 0;
        __syncthreads();
#pragma unroll
        for (int j = 0; j < 8; j++)
            if ((u[j] & mask) == prefix)
                atomicAdd(&hist[(u[j] >> (by * 8)) & 255], 1);
        __syncthreads();
        if (t == 0) {
            int cum = 0, d = 255;
            for (; d > 0; d--) { cum += hist[d]; if (cum >= k) break; }
            if (cum < k) cum += hist[0];
            sh_pref = prefix | ((unsigned)d << (by * 8));
            sh_k = k - (cum - hist[d]);
        }
        __syncthreads();
        prefix = sh_pref; k = sh_k;
        mask |= (0xFFu << (by * 8));
        __syncthreads();
    }
    const unsigned th = prefix;

    // dense fp16 output
#pragma unroll
    for (int j = 0; j < 8; j++) {
        float o = (u[j] >= th) ? v[j] : 0.0f;
        hd[(size_t)row * HID + t + 256 * j] = __float2half(o);
    }

    // compaction (fallback path)
    int n = 0;
    bool act[8];
#pragma unroll
    for (int j = 0; j < 8; j++) { act[j] = (u[j] >= th); n += act[j] ? 1 : 0; }
    int incl = n;
#pragma unroll
    for (int o = 1; o < 32; o <<= 1) {
        int y = __shfl_up_sync(0xFFFFFFFFu, incl, o);
        if (lane >= o) incl += y;
    }
    if (lane == 31) wsum[w] = incl;
    __syncthreads();
    if (t == 0) {
        int a = 0;
#pragma unroll
        for (int i = 0; i < 8; i++) { int b = wsum[i]; wsum[i] = a; a += b; }
        s_tot = (a > NCAP) ? NCAP : a;
    }
    __syncthreads();
    int pos = wsum[w] + incl - n;
#pragma unroll
    for (int j = 0; j < 8; j++) {
        if (act[j] && pos < NCAP) { s_val[pos] = v[j]; s_idx[pos] = t + 256 * j; pos++; }
    }
    __syncthreads();
    int tot = s_tot;
    if (t < NCAP) {
        gv[(size_t)row * NCAP + t] = (t < tot) ? s_val[t] : 0.0f;
        gi[(size_t)row * NCAP + t] = (t < tot) ? s_idx[t] : 0;
    }
    if (t == 0) gc[row] = tot;
}

// ---- sparse layer 3 (fallback) ----
__global__ void __launch_bounds__(256) sparse_out_kernel(
    const float* __restrict__ gv, const int* __restrict__ gi, const int* __restrict__ gc,
    const __half* __restrict__ W3, const float* __restrict__ b3, float* __restrict__ out)
{
    __shared__ float sv[NCAP];
    __shared__ int si[NCAP];
    const int row = blockIdx.x, ch = blockIdx.y, t = threadIdx.x;
    if (t < NCAP) {
        sv[t] = gv[(size_t)row * NCAP + t];
        si[t] = gi[(size_t)row * NCAP + t];
    }
    __syncthreads();
    const int cnt = gc[row];
    const int c0 = ch * CCH + 8 * t;

    float a[8] = {0, 0, 0, 0, 0, 0, 0, 0};
#pragma unroll 2
    for (int k = 0; k < cnt; k++) {
        float vv = sv[k];
        uint4 q = *(const uint4*)(W3 + (size_t)si[k] * D_IN + c0);
        float2 p;
        p = __half22float2(*(__half2*)&q.x); a[0] += vv * p.x; a[1] += vv * p.y;
        p = __half22float2(*(__half2*)&q.y); a[2] += vv * p.x; a[3] += vv * p.y;
        p = __half22float2(*(__half2*)&q.z); a[4] += vv * p.x; a[5] += vv * p.y;
        p = __half22float2(*(__half2*)&q.w); a[6] += vv * p.x; a[7] += vv * p.y;
    }
    float4 b0 = *(const float4*)(b3 + c0);
    float4 b1 = *(const float4*)(b3 + c0 + 4);
    float4 o0, o1;
    o0.x = 1.0f / (1.0f + __expf(-(a[0] + b0.x)));
    o0.y = 1.0f / (1.0f + __expf(-(a[1] + b0.y)));
    o0.z = 1.0f / (1.0f + __expf(-(a[2] + b0.z)));
    o0.w = 1.0f / (1.0f + __expf(-(a[3] + b0.w)));
    o1.x = 1.0f / (1.0f + __expf(-(a[4] + b1.x)));
    o1.y = 1.0f / (1.0f + __expf(-(a[5] + b1.y)));
    o1.z = 1.0f / (1.0f + __expf(-(a[6] + b1.z)));
    o1.w = 1.0f / (1.0f + __expf(-(a[7] + b1.w)));
    float* op = out + (size_t)row * D_IN + c0;
    *(float4*)(op)     = o0;
    *(float4*)(op + 4) = o1;
}

// ---- shared epilogue ----
template <int EPI>
DINL void gemm_epilogue(float c[2][8][4], int mtile, int ntile, int m0, int n0,
                        int g, int t, const float* bias, float* out_f,
                        __nv_bfloat16* out_h, __nv_bfloat16* out_l, int ldo)
{
#pragma unroll
    for (int i = 0; i < 2; i++) {
        int r0 = mtile * 128 + m0 + i * 16 + g;
#pragma unroll
        for (int j = 0; j < 8; j++) {
            int col = ntile * 128 + n0 + j * 8 + 2 * t;
            float2 bb = *(const float2*)&bias[col];
            float v0 = c[i][j][0] + bb.x, v1 = c[i][j][1] + bb.y;
            float v2 = c[i][j][2] + bb.x, v3 = c[i][j][3] + bb.y;
            if (EPI == 0) {
                v0 = fmaxf(v0, 0.0f); v1 = fmaxf(v1, 0.0f);
                v2 = fmaxf(v2, 0.0f); v3 = fmaxf(v3, 0.0f);
                __nv_bfloat16 h0 = __float2bfloat16(v0), h1 = __float2bfloat16(v1);
                __nv_bfloat16 h2 = __float2bfloat16(v2), h3 = __float2bfloat16(v3);
                *(uint32_t*)&out_h[(size_t)r0 * ldo + col]       = pack_bf2(h0, h1);
                *(uint32_t*)&out_h[(size_t)(r0 + 8) * ldo + col] = pack_bf2(h2, h3);
                *(uint32_t*)&out_l[(size_t)r0 * ldo + col] =
                    pack_bf2(__float2bfloat16(v0 - __bfloat162float(h0)),
                             __float2bfloat16(v1 - __bfloat162float(h1)));
                *(uint32_t*)&out_l[(size_t)(r0 + 8) * ldo + col] =
                    pack_bf2(__float2bfloat16(v2 - __bfloat162float(h2)),
                             __float2bfloat16(v3 - __bfloat162float(h3)));
            } else if (EPI == 1) {
                *(float2*)&out_f[(size_t)r0 * ldo + col]       = make_float2(v0, v1);
                *(float2*)&out_f[(size_t)(r0 + 8) * ldo + col] = make_float2(v2, v3);
            } else {
                float s0 = 1.0f / (1.0f + __expf(-v0));
                float s1 = 1.0f / (1.0f + __expf(-v1));
                float s2 = 1.0f / (1.0f + __expf(-v2));
                float s3 = 1.0f / (1.0f + __expf(-v3));
                *(float2*)&out_f[(size_t)r0 * ldo + col]       = make_float2(s0, s1);
                *(float2*)&out_f[(size_t)(r0 + 8) * ldo + col] = make_float2(s2, s3);
            }
        }
    }
}

// ---- TMA GEMM (NPASS=3: split-bf16; NPASS=1: plain fp16) ----
template <int EPI, int NPASS>
__global__ void __launch_bounds__(256, 1) gemm_tma(
    const __grid_constant__ CUtensorMap mAh, const __grid_constant__ CUtensorMap mAl,
    const __grid_constant__ CUtensorMap mBh, const __grid_constant__ CUtensorMap mBl,
    const float* __restrict__ bias, int K,
    float* __restrict__ out_f,
    __nv_bfloat16* __restrict__ out_h, __nv_bfloat16* __restrict__ out_l, int ldo)
{
    constexpr uint32_t SBYTES = (NPASS == 3) ? 65536u : 32768u;
    extern __shared__ __align__(16) char smem[];
    __shared__ __align__(8) uint64_t mbars[6];
    const int tid = threadIdx.x;
    const int wid = tid >> 5, lane = tid & 31;
    const int g = lane >> 2, t = lane & 3;
    const int m4 = lane >> 3, r8 = lane & 7;
    const int m0 = (wid & 3) * 32, n0 = (wid >> 2) * 64;
    const int mtile = blockIdx.x, ntile = blockIdx.y;
    const int KT = K / 64;
    const uint32_t base = (smem_u32(smem) + 1023u) & ~1023u;
    const uint32_t mb = smem_u32(mbars);

    float c[2][8][4];
#pragma unroll
    for (int i = 0; i < 2; i++)
#pragma unroll
        for (int j = 0; j < 8; j++)
#pragma unroll
            for (int q = 0; q < 4; q++) c[i][j][q] = 0.0f;

    uint32_t baA[2], xmA[2], baB[4], xmB[4];
    const uint32_t selA = (uint32_t)((m4 >> 1) << 4);
    const uint32_t selB = (uint32_t)((m4 & 1) << 4);
#pragma unroll
    for (int i = 0; i < 2; i++) {
        uint32_t r = (uint32_t)(m0 + i * 16 + ((m4 & 1) << 3) + r8);
        baA[i] = r * 128u;
        xmA[i] = (r & 7u) << 4;
    }
#pragma unroll
    for (int q = 0; q < 4; q++) {
        uint32_t r = (uint32_t)(n0 + (2 * q + (m4 >> 1)) * 8 + r8);
        baB[q] = r * 128u;
        xmB[q] = (r & 7u) << 4;
    }

    if (tid == 0) {
#pragma unroll
        for (int s = 0; s < 3; s++) { mbar_init(mb + 8 * s, 1); mbar_init(mb + 24 + 8 * s, 8); }
    }
    __syncthreads();

    auto issue = [&](int kt) {
        int buf = kt % 3;
        uint32_t sb = base + (uint32_t)buf * SBYTES;
        uint32_t fb = mb + 8 * buf;
        mbar_expect(fb, SBYTES);
        tma2d(sb, &mAh, kt * 64, mtile * 128, fb);
        if (NPASS == 3) {
            tma2d(sb + TTILE,     &mAl, kt * 64, mtile * 128, fb);
            tma2d(sb + 2 * TTILE, &mBh, kt * 64, ntile * 128, fb);
            tma2d(sb + 3 * TTILE, &mBl, kt * 64, ntile * 128, fb);
        } else {
            tma2d(sb + TTILE, &mBh, kt * 64, ntile * 128, fb);
        }
    };

    if (tid == 0) {
        int np = KT < 3 ? KT : 3;
        for (int p = 0; p < np; p++) issue(p);
    }

#pragma unroll 1
    for (int kt = 0; kt < KT; kt++) {
        const int buf = kt % 3;
        const uint32_t ph = (uint32_t)((kt / 3) & 1);
        mbar_wait(mb + 8 * buf, ph);

        const uint32_t sA = base + (uint32_t)buf * SBYTES;
        const uint32_t sAl = sA + TTILE;
        const uint32_t sBh = (NPASS == 3) ? (sA + 2 * TTILE) : (sA + TTILE);
        const uint32_t sBl = sA + 3 * TTILE;

#pragma unroll
        for (int kk = 0; kk < 4; kk++) {
            const uint32_t cbA = (uint32_t)(kk * 32) + selA;
            const uint32_t cbB = (uint32_t)(kk * 32) + selB;
            uint32_t ah[2][4], al[2][4], bh[8][2], bl[8][2];
#pragma unroll
            for (int i = 0; i < 2; i++) {
                uint32_t o = baA[i] + (cbA ^ xmA[i]);
                ldsm4(ah[i][0], ah[i][1], ah[i][2], ah[i][3], sA + o);
                if (NPASS == 3)
                    ldsm4(al[i][0], al[i][1], al[i][2], al[i][3], sAl + o);
            }
#pragma unroll
            for (int q = 0; q < 4; q++) {
                uint32_t o = baB[q] + (cbB ^ xmB[q]);
                ldsm4(bh[2 * q][0], bh[2 * q][1], bh[2 * q + 1][0], bh[2 * q + 1][1], sBh + o);
                if (NPASS == 3)
                    ldsm4(bl[2 * q][0], bl[2 * q][1], bl[2 * q + 1][0], bl[2 * q + 1][1], sBl + o);
            }
#pragma unroll
            for (int i = 0; i < 2; i++)
#pragma unroll
                for (int j = 0; j < 8; j++) {
                    if (NPASS == 3) {
                        mma_bf16(c[i][j], ah[i][0], ah[i][1], ah[i][2], ah[i][3], bh[j][0], bh[j][1]);
                        mma_bf16(c[i][j], ah[i][0], ah[i][1], ah[i][2], ah[i][3], bl[j][0], bl[j][1]);
                        mma_bf16(c[i][j], al[i][0], al[i][1], al[i][2], al[i][3], bh[j][0], bh[j][1]);
                    } else {
                        mma_fp16(c[i][j], ah[i][0], ah[i][1], ah[i][2], ah[i][3], bh[j][0], bh[j][1]);
                    }
                }
        }

        if (elect_one()) mbar_arrive(mb + 24 + 8 * buf);
        if (tid == 0 && kt + 3 < KT) {
            mbar_wait(mb + 24 + 8 * buf, ph);
            issue(kt + 3);
        }
    }

    gemm_epilogue<EPI>(c, mtile, ntile, m0, n0, g, t, bias, out_f, out_h, out_l, ldo);
}

// ---- fallback cp.async split-bf16 GEMM ----
template <int EPI>
__global__ void __launch_bounds__(256, 1) gemm_kernel(
    const __nv_bfloat16* __restrict__ Ah, const __nv_bfloat16* __restrict__ Al,
    const __nv_bfloat16* __restrict__ Bh, const __nv_bfloat16* __restrict__ Bl,
    const float* __restrict__ bias, int K,
    float* __restrict__ out_f,
    __nv_bfloat16* __restrict__ out_h, __nv_bfloat16* __restrict__ out_l, int ldo)
{
    extern __shared__ __align__(16) char smem[];
    const int tid = threadIdx.x;
    const int wid = tid >> 5, lane = tid & 31;
    const int g = lane >> 2, t = lane & 3;
    const int m4 = lane >> 3, r8 = lane & 7;
    const int m0 = (wid & 3) * 32, n0 = (wid >> 2) * 64;
    const int mtile = blockIdx.x, ntile = blockIdx.y;
    const int KT = K / TKT;
    const __nv_bfloat16* gbase[4] = { Ah, Al, Bh, Bl };

    float c[2][8][4];
#pragma unroll
    for (int i = 0; i < 2; i++)
#pragma unroll
        for (int j = 0; j < 8; j++)
#pragma unroll
            for (int q = 0; q < 4; q++) c[i][j][q] = 0.0f;

    uint32_t offA[2], offB[4];
#pragma unroll
    for (int i = 0; i < 2; i++)
        offA[i] = (uint32_t)(((m0 + i * 16 + ((m4 & 1) << 3) + r8) * SROW
                              + ((m4 >> 1) << 3)) * 2);
#pragma unroll
    for (int q = 0; q < 4; q++)
        offB[q] = (uint32_t)(((n0 + (2 * q + (m4 >> 1)) * 8 + r8) * SROW
                              + ((m4 & 1) << 3)) * 2);

    const uint32_t sb0 = smem_u32(smem);

    auto load_stage = [&](int kt, int buf) {
        char* sb = smem + buf * STAGE_BYTES;
#pragma unroll
        for (int i = 0; i < 16; i++) {
            int id = tid + 256 * i;
            int arr = id >> 10;
            int rem = id & 1023;
            int row = rem >> 3, chunk = rem & 7;
            int grow = ((arr < 2) ? mtile : ntile) * 128 + row;
            const char* src = (const char*)(gbase[arr] + (size_t)grow * K + (size_t)kt * TKT)
                              + chunk * 16;
            uint32_t dst = smem_u32(sb + arr * TILE_BYTES + row * (SROW * 2) + chunk * 16);
            cp16(dst, src);
        }
    };

    load_stage(0, 0);
    cp_commit();
    load_stage(1, 1);
    cp_commit();

#pragma unroll 1
    for (int kt = 0; kt < KT; kt++) {
        if (kt + 1 < KT) cp_wait<1>(); else cp_wait<0>();
        __syncthreads();
        if (kt + 2 < KT) { load_stage(kt + 2, (kt + 2) % NSTAGE); cp_commit(); }

        const uint32_t sA = sb0 + (kt % NSTAGE) * STAGE_BYTES;
        const uint32_t sB = sA + 2 * TILE_BYTES;

#pragma unroll
        for (int kk = 0; kk < 4; kk++) {
            const uint32_t kb = (uint32_t)kk * 32;
            uint32_t ah[2][4], al[2][4], bh[8][2], bl[8][2];
#pragma unroll
            for (int i = 0; i < 2; i++) {
                ldsm4(ah[i][0], ah[i][1], ah[i][2], ah[i][3], sA + offA[i] + kb);
                ldsm4(al[i][0], al[i][1], al[i][2], al[i][3], sA + TILE_BYTES + offA[i] + kb);
            }
#pragma unroll
            for (int q = 0; q < 4; q++) {
                ldsm4(bh[2 * q][0], bh[2 * q][1], bh[2 * q + 1][0], bh[2 * q + 1][1],
                      sB + offB[q] + kb);
                ldsm4(bl[2 * q][0], bl[2 * q][1], bl[2 * q + 1][0], bl[2 * q + 1][1],
                      sB + TILE_BYTES + offB[q] + kb);
            }
#pragma unroll
            for (int i = 0; i < 2; i++)
#pragma unroll
                for (int j = 0; j < 8; j++) {
                    mma_bf16(c[i][j], ah[i][0], ah[i][1], ah[i][2], ah[i][3], bh[j][0], bh[j][1]);
                    mma_bf16(c[i][j], ah[i][0], ah[i][1], ah[i][2], ah[i][3], bl[j][0], bl[j][1]);
                    mma_bf16(c[i][j], al[i][0], al[i][1], al[i][2], al[i][3], bh[j][0], bh[j][1]);
                }
        }
        __syncthreads();
    }

    gemm_epilogue<EPI>(c, mtile, ntile, m0, n0, g, t, bias, out_f, out_h, out_l, ldo);
}

// ---- host ----
template <typename T> static T* sym(const void* s) {
    void* p = nullptr;
    cudaGetSymbolAddress(&p, s);
    return (T*)p;
}

typedef CUresult (*EncFn)(CUtensorMap*, CUtensorMapDataType, cuuint32_t, void*,
                          const cuuint64_t*, const cuuint64_t*, const cuuint32_t*,
                          const cuuint32_t*, CUtensorMapInterleave, CUtensorMapSwizzle,
                          CUtensorMapL2promotion, CUtensorMapFloatOOBfill);

static bool enc2d(EncFn enc, CUtensorMap* m, void* ptr, uint64_t K, uint64_t R,
                  CUtensorMapDataType dt) {
    cuuint64_t dims[2] = { K, R };
    cuuint64_t strides[1] = { K * 2 };
    cuuint32_t box[2] = { 64, 128 };
    cuuint32_t es[2] = { 1, 1 };
    return enc(m, dt, 2, ptr, dims, strides, box, es,
               CU_TENSOR_MAP_INTERLEAVE_NONE, CU_TENSOR_MAP_SWIZZLE_128B,
               CU_TENSOR_MAP_L2_PROMOTION_L2_128B,
               CU_TENSOR_MAP_FLOAT_OOB_FILL_NONE) == CUDA_SUCCESS;
}

extern "C" void kernel_launch(void* const* d_in, const int* in_sizes, int n_in,
                              void* d_out, int out_size)
{
    const float* X  = (const float*)d_in[0];
    const float* W1 = (const float*)d_in[1];
    const float* b1 = (const float*)d_in[2];
    const float* W2 = (const float*)d_in[3];
    const float* b2 = (const float*)d_in[4];
    const float* W3 = (const float*)d_in[5];
    const float* b3 = (const float*)d_in[6];
    const int* knb  = (const int*)d_in[7];
    float* out = (float*)d_out;

    __nv_bfloat16* Xh  = sym<__nv_bfloat16>(g_Xh);
    __nv_bfloat16* Xl  = sym<__nv_bfloat16>(g_Xl);
    __nv_bfloat16* W1h = sym<__nv_bfloat16>(g_W1h);
    __nv_bfloat16* W1l = sym<__nv_bfloat16>(g_W1l);
    __nv_bfloat16* W2h = sym<__nv_bfloat16>(g_W2h);
    __nv_bfloat16* W2l = sym<__nv_bfloat16>(g_W2l);
    __half*        W3t = sym<__half>(g_W3t);
    __half*        W3f = sym<__half>(g_W3f);
    __nv_bfloat16* H1h = sym<__nv_bfloat16>(g_H1h);
    __nv_bfloat16* H1l = sym<__nv_bfloat16>(g_H1l);
    float*         H2  = sym<float>(g_H2);
    __half*        H2s = sym<__half>(g_H2s);
    float*         gv  = sym<float>(g_sv);
    int*           gi  = sym<int>(g_si);
    int*           gc  = sym<int>(g_sc);

    void* h = dlopen("libcuda.so.1", RTLD_LAZY | RTLD_GLOBAL);
    if (!h) h = dlopen("libcuda.so", RTLD_LAZY | RTLD_GLOBAL);
    EncFn enc = h ? (EncFn)dlsym(h, "cuTensorMapEncodeTiled") : nullptr;
    CUtensorMap mXh, mXl, mW1h, mW1l, mH1h, mH1l, mW2h, mW2l, mH2s, mW3t;
    bool tma_ok = (enc != nullptr);
    if (tma_ok) {
        const CUtensorMapDataType BF = CU_TENSOR_MAP_DATA_TYPE_BFLOAT16;
        const CUtensorMapDataType F16 = CU_TENSOR_MAP_DATA_TYPE_FLOAT16;
        tma_ok = enc2d(enc, &mXh, Xh, D_IN, B_ROWS, BF) && enc2d(enc, &mXl, Xl, D_IN, B_ROWS, BF)
              && enc2d(enc, &mW1h, W1h, D_IN, HID, BF)  && enc2d(enc, &mW1l, W1l, D_IN, HID, BF)
              && enc2d(enc, &mH1h, H1h, HID, B_ROWS, BF) && enc2d(enc, &mH1l, H1l, HID, B_ROWS, BF)
              && enc2d(enc, &mW2h, W2h, HID, HID, BF)   && enc2d(enc, &mW2l, W2l, HID, HID, BF)
              && enc2d(enc, &mH2s, H2s, HID, B_ROWS, F16) && enc2d(enc, &mW3t, W3t, HID, D_IN, F16);
    }

    cudaFuncSetAttribute(gemm_tma<0, 3>, cudaFuncAttributeMaxDynamicSharedMemorySize, TSMEM);
    cudaFuncSetAttribute(gemm_tma<1, 3>, cudaFuncAttributeMaxDynamicSharedMemorySize, TSMEM);
    cudaFuncSetAttribute(gemm_tma<2, 1>, cudaFuncAttributeMaxDynamicSharedMemorySize, TSMEM);
    cudaFuncSetAttribute(gemm_kernel<0>, cudaFuncAttributeMaxDynamicSharedMemorySize, SMEM_DYN);
    cudaFuncSetAttribute(gemm_kernel<1>, cudaFuncAttributeMaxDynamicSharedMemorySize, SMEM_DYN);

    // 1. split X
    size_t n4 = (size_t)B_ROWS * D_IN / 4;
    split_kernel<<<(unsigned)((n4 + 255) / 256), 256>>>((const float4*)X, (uint2*)Xh, (uint2*)Xl, n4);

    // 2. weight prep
    dim3 t8(32, 8);
    tsplit_kernel<<<dim3(HID / 32, D_IN / 32), t8>>>(W1, W1h, W1l, D_IN, HID);
    tsplit_kernel<<<dim3(HID / 32, HID / 32), t8>>>(W2, W2h, W2l, HID, HID);
    if (tma_ok) {
        ttrans_h_kernel<<<dim3(D_IN / 32, HID / 32), t8>>>(W3, W3t, HID, D_IN);
    } else {
        size_t w34 = (size_t)HID * D_IN / 4;
        htrunc_kernel<<<(unsigned)((w34 + 255) / 256), 256>>>((const float4*)W3, (uint2*)W3f, w34);
    }

    // 3+4. GEMMs
    if (tma_ok) {
        gemm_tma<0, 3><<<dim3(B_ROWS / 128, HID / 128), 256, TSMEM>>>(
            mXh, mXl, mW1h, mW1l, b1, D_IN, nullptr, H1h, H1l, HID);
        gemm_tma<1, 3><<<dim3(B_ROWS / 128, HID / 128), 256, TSMEM>>>(
            mH1h, mH1l, mW2h, mW2l, b2, HID, H2, nullptr, nullptr, HID);
    } else {
        gemm_kernel<0><<<dim3(B_ROWS / TMT, HID / TNT), 256, SMEM_DYN>>>(
            Xh, Xl, W1h, W1l, b1, D_IN, nullptr, H1h, H1l, HID);
        gemm_kernel<1><<<dim3(B_ROWS / TMT, HID / TNT), 256, SMEM_DYN>>>(
            H1h, H1l, W2h, W2l, b2, HID, H2, nullptr, nullptr, HID);
    }

    // 5. top-k -> dense fp16 sparsified (+ compaction for fallback)
    topk_kernel<<<B_ROWS, 256>>>(H2, knb, H2s, gv, gi, gc);

    // 6. layer 3
    if (tma_ok) {
        gemm_tma<2, 1><<<dim3(B_ROWS / 128, D_IN / 128), 256, TSMEM>>>(
            mH2s, mH2s, mW3t, mW3t, b3, HID, out, nullptr, nullptr, D_IN);
    } else {
        sparse_out_kernel<<<dim3(B_ROWS, D_IN / CCH), 256>>>(gv, gi, gc, W3f, b3, out);
    }

    (void)in_sizes; (void)n_in; (void)out_size;
}

// round 13
// speedup vs baseline: 1.1200x; 1.1200x over previous
#include <cuda_runtime.h>
#include <cuda.h>
#include <cuda_bf16.h>
#include <cuda_fp16.h>
#include <cstdint>
#include <cstddef>
#include <dlfcn.h>

#define DINL __device__ __forceinline__

#define B_ROWS 8192
#define D_IN   12288
#define HID    2048
#define NCAP   96
#define CCH    2048

// ---- fallback (cp.async) GEMM tiling ----
#define TMT 128
#define TNT 128
#define TKT 64
#define SROW 72
#define TILE_BYTES (128 * SROW * 2)
#define STAGE_BYTES (4 * TILE_BYTES)
#define NSTAGE 3
#define SMEM_DYN (NSTAGE * STAGE_BYTES)

// ---- TMA GEMM tiling ----
#define TTILE 16384                       // 128 rows x 128 B
#define TSTAGE 65536                      // 4 tiles
#define TSMEM (3 * TSTAGE + 1024)

// ---- scratch ----
static __device__ __nv_bfloat16 g_Xh [(size_t)B_ROWS * D_IN];
static __device__ __nv_bfloat16 g_Xl [(size_t)B_ROWS * D_IN];
static __device__ __nv_bfloat16 g_W1h[(size_t)HID * D_IN];
static __device__ __nv_bfloat16 g_W1l[(size_t)HID * D_IN];
static __device__ __nv_bfloat16 g_W2h[(size_t)HID * HID];
static __device__ __nv_bfloat16 g_W2l[(size_t)HID * HID];
static __device__ __half        g_W3f [(size_t)HID * D_IN];
static __device__ __nv_bfloat16 g_H1h[(size_t)B_ROWS * HID];
static __device__ __nv_bfloat16 g_H1l[(size_t)B_ROWS * HID];
static __device__ float         g_H2 [(size_t)B_ROWS * HID];
static __device__ float         g_sv [(size_t)B_ROWS * NCAP];
static __device__ int           g_si [(size_t)B_ROWS * NCAP];
static __device__ int           g_sc [B_ROWS];

// ---- helpers ----
DINL uint32_t smem_u32(const void* p) {
    uint32_t a;
    asm("{ .reg .u64 t; cvta.to.shared.u64 t, %1; cvt.u32.u64 %0, t; }" : "=r"(a) : "l"(p));
    return a;
}
DINL bool elect_one() {
    uint32_t p;
    asm volatile("{ .reg .pred p; elect.sync _|p, 0xFFFFFFFF; selp.b32 %0, 1, 0, p; }" : "=r"(p));
    return p != 0;
}
DINL void cp16(uint32_t d, const void* s) {
    asm volatile("cp.async.cg.shared.global [%0], [%1], 16;" :: "r"(d), "l"(s));
}
DINL void cp_commit() { asm volatile("cp.async.commit_group;" ::: "memory"); }
template <int N> DINL void cp_wait() {
    asm volatile("cp.async.wait_group %0;" :: "n"(N) : "memory");
}
DINL void ldsm4(uint32_t& r0, uint32_t& r1, uint32_t& r2, uint32_t& r3, uint32_t addr) {
    asm volatile("ldmatrix.sync.aligned.m8n8.x4.shared.b16 {%0,%1,%2,%3}, [%4];"
                 : "=r"(r0), "=r"(r1), "=r"(r2), "=r"(r3) : "r"(addr));
}
DINL void mma_bf16(float* c, uint32_t a0, uint32_t a1, uint32_t a2, uint32_t a3,
                   uint32_t b0, uint32_t b1) {
    asm volatile(
        "mma.sync.aligned.m16n8k16.row.col.f32.bf16.bf16.f32 "
        "{%0,%1,%2,%3},{%4,%5,%6,%7},{%8,%9},{%0,%1,%2,%3};"
        : "+f"(c[0]), "+f"(c[1]), "+f"(c[2]), "+f"(c[3])
        : "r"(a0), "r"(a1), "r"(a2), "r"(a3), "r"(b0), "r"(b1));
}
DINL uint32_t pack_bf2(__nv_bfloat16 a, __nv_bfloat16 b) {
    return (uint32_t)__bfloat16_as_ushort(a) | ((uint32_t)__bfloat16_as_ushort(b) << 16);
}
DINL void mbar_init(uint32_t a, uint32_t c) {
    asm volatile("mbarrier.init.shared.b64 [%0], %1;" :: "r"(a), "r"(c) : "memory");
}
DINL void mbar_arrive(uint32_t a) {
    asm volatile("mbarrier.arrive.shared.b64 _, [%0];" :: "r"(a) : "memory");
}
DINL void mbar_expect(uint32_t a, uint32_t bytes) {
    asm volatile("mbarrier.arrive.expect_tx.shared.b64 _, [%0], %1;"
                 :: "r"(a), "r"(bytes) : "memory");
}
DINL void mbar_wait(uint32_t a, uint32_t par) {
    asm volatile(
        "{\n\t.reg .pred P;\n\t"
        "WL%=:\n\t"
        "mbarrier.try_wait.parity.acquire.cta.shared::cta.b64 P, [%0], %1, 0x989680;\n\t"
        "@P bra WD%=;\n\t"
        "bra WL%=;\n\t"
        "WD%=:\n\t}"
        :: "r"(a), "r"(par) : "memory");
}
DINL void tma2d(uint32_t dst, const void* map, int cx, int cy, uint32_t mbar) {
    asm volatile(
        "cp.async.bulk.tensor.2d.shared::cta.global.tile.mbarrier::complete_tx::bytes "
        "[%0], [%1, {%2, %3}], [%4];"
        :: "r"(dst), "l"(map), "r"(cx), "r"(cy), "r"(mbar) : "memory");
}

// ---- split X ----
__global__ void __launch_bounds__(256) split_kernel(
    const float4* __restrict__ src, uint2* __restrict__ dh, uint2* __restrict__ dl, size_t n4)
{
    size_t i = (size_t)blockIdx.x * 256u + threadIdx.x;
    if (i >= n4) return;
    float4 x = src[i];
    __nv_bfloat16 h0 = __float2bfloat16(x.x), h1 = __float2bfloat16(x.y);
    __nv_bfloat16 h2 = __float2bfloat16(x.z), h3 = __float2bfloat16(x.w);
    dh[i] = make_uint2(pack_bf2(h0, h1), pack_bf2(h2, h3));
    dl[i] = make_uint2(
        pack_bf2(__float2bfloat16(x.x - __bfloat162float(h0)),
                 __float2bfloat16(x.y - __bfloat162float(h1))),
        pack_bf2(__float2bfloat16(x.z - __bfloat162float(h2)),
                 __float2bfloat16(x.w - __bfloat162float(h3))));
}

// ---- transpose + split weights ----
__global__ void __launch_bounds__(256) tsplit_kernel(
    const float* __restrict__ src, __nv_bfloat16* __restrict__ dh,
    __nv_bfloat16* __restrict__ dl, int R, int C)
{
    __shared__ float tile[32][33];
    int c0 = blockIdx.x * 32, r0 = blockIdx.y * 32;
    int tx = threadIdx.x, ty = threadIdx.y;
#pragma unroll
    for (int j = 0; j < 32; j += 8)
        tile[ty + j][tx] = src[(size_t)(r0 + ty + j) * C + (c0 + tx)];
    __syncthreads();
#pragma unroll
    for (int j = 0; j < 32; j += 8) {
        float v = tile[tx][ty + j];
        size_t o = (size_t)(c0 + ty + j) * R + (r0 + tx);
        __nv_bfloat16 h = __float2bfloat16(v);
        dh[o] = h;
        dl[o] = __float2bfloat16(v - __bfloat162float(h));
    }
}

// ---- W3 f32 -> fp16 ----
__global__ void __launch_bounds__(256) htrunc_kernel(
    const float4* __restrict__ src, uint2* __restrict__ dst, size_t n4)
{
    size_t i = (size_t)blockIdx.x * 256u + threadIdx.x;
    if (i >= n4) return;
    float4 x = src[i];
    __half2 lo = __floats2half2_rn(x.x, x.y);
    __half2 hi = __floats2half2_rn(x.z, x.w);
    dst[i] = make_uint2(*(uint32_t*)&lo, *(uint32_t*)&hi);
}

// ---- exact top-k threshold + deterministic compaction ----
DINL unsigned fmap(float x) {
    unsigned b = __float_as_uint(x);
    return (b & 0x80000000u) ? ~b : (b | 0x80000000u);
}
__global__ void __launch_bounds__(256) topk_kernel(
    const float* __restrict__ H2, const int* __restrict__ knb,
    float* __restrict__ gv, int* __restrict__ gi, int* __restrict__ gc)
{
    __shared__ int hist[256];
    __shared__ unsigned sh_pref;
    __shared__ int sh_k;
    __shared__ float s_val[NCAP];
    __shared__ int s_idx[NCAP];
    __shared__ int wsum[8];
    __shared__ int s_tot;
    const int row = blockIdx.x, t = threadIdx.x;
    const int lane = t & 31, w = t >> 5;
    const float* rp = H2 + (size_t)row * HID;
    float v[8]; unsigned u[8];
#pragma unroll
    for (int j = 0; j < 8; j++) { v[j] = rp[t + 256 * j]; u[j] = fmap(v[j]); }
    int k = *knb;
    unsigned prefix = 0, mask = 0;
#pragma unroll 1
    for (int by = 3; by >= 0; by--) {
        hist[t] = 0;
        __syncthreads();
#pragma unroll
        for (int j = 0; j < 8; j++)
            if ((u[j] & mask) == prefix)
                atomicAdd(&hist[(u[j] >> (by * 8)) & 255], 1);
        __syncthreads();
        if (t == 0) {
            int cum = 0, d = 255;
            for (; d > 0; d--) { cum += hist[d]; if (cum >= k) break; }
            if (cum < k) cum += hist[0];
            sh_pref = prefix | ((unsigned)d << (by * 8));
            sh_k = k - (cum - hist[d]);
        }
        __syncthreads();
        prefix = sh_pref; k = sh_k;
        mask |= (0xFFu << (by * 8));
        __syncthreads();
    }
    const unsigned th = prefix;

    int n = 0;
    bool act[8];
#pragma unroll
    for (int j = 0; j < 8; j++) { act[j] = (u[j] >= th); n += act[j] ? 1 : 0; }
    int incl = n;
#pragma unroll
    for (int o = 1; o < 32; o <<= 1) {
        int y = __shfl_up_sync(0xFFFFFFFFu, incl, o);
        if (lane >= o) incl += y;
    }
    if (lane == 31) wsum[w] = incl;
    __syncthreads();
    if (t == 0) {
        int a = 0;
#pragma unroll
        for (int i = 0; i < 8; i++) { int b = wsum[i]; wsum[i] = a; a += b; }
        s_tot = (a > NCAP) ? NCAP : a;
    }
    __syncthreads();
    int pos = wsum[w] + incl - n;
#pragma unroll
    for (int j = 0; j < 8; j++) {
        if (act[j] && pos < NCAP) { s_val[pos] = v[j]; s_idx[pos] = t + 256 * j; pos++; }
    }
    __syncthreads();
    int tot = s_tot;
    if (t < NCAP) {
        gv[(size_t)row * NCAP + t] = (t < tot) ? s_val[t] : 0.0f;
        gi[(size_t)row * NCAP + t] = (t < tot) ? s_idx[t] : 0;
    }
    if (t == 0) gc[row] = tot;
}

// ---- sparse layer 3 (fp16 W3, one uint4 load per k) ----
__global__ void __launch_bounds__(256) sparse_out_kernel(
    const float* __restrict__ gv, const int* __restrict__ gi, const int* __restrict__ gc,
    const __half* __restrict__ W3, const float* __restrict__ b3, float* __restrict__ out)
{
    __shared__ float sv[NCAP];
    __shared__ int si[NCAP];
    const int row = blockIdx.x, ch = blockIdx.y, t = threadIdx.x;
    if (t < NCAP) {
        sv[t] = gv[(size_t)row * NCAP + t];
        si[t] = gi[(size_t)row * NCAP + t];
    }
    __syncthreads();
    const int cnt = gc[row];
    const int c0 = ch * CCH + 8 * t;

    float a[8] = {0, 0, 0, 0, 0, 0, 0, 0};
#pragma unroll 2
    for (int k = 0; k < cnt; k++) {
        float vv = sv[k];
        uint4 q = *(const uint4*)(W3 + (size_t)si[k] * D_IN + c0);
        float2 p;
        p = __half22float2(*(__half2*)&q.x); a[0] += vv * p.x; a[1] += vv * p.y;
        p = __half22float2(*(__half2*)&q.y); a[2] += vv * p.x; a[3] += vv * p.y;
        p = __half22float2(*(__half2*)&q.z); a[4] += vv * p.x; a[5] += vv * p.y;
        p = __half22float2(*(__half2*)&q.w); a[6] += vv * p.x; a[7] += vv * p.y;
    }
    float4 b0 = *(const float4*)(b3 + c0);
    float4 b1 = *(const float4*)(b3 + c0 + 4);
    float4 o0, o1;
    o0.x = 1.0f / (1.0f + __expf(-(a[0] + b0.x)));
    o0.y = 1.0f / (1.0f + __expf(-(a[1] + b0.y)));
    o0.z = 1.0f / (1.0f + __expf(-(a[2] + b0.z)));
    o0.w = 1.0f / (1.0f + __expf(-(a[3] + b0.w)));
    o1.x = 1.0f / (1.0f + __expf(-(a[4] + b1.x)));
    o1.y = 1.0f / (1.0f + __expf(-(a[5] + b1.y)));
    o1.z = 1.0f / (1.0f + __expf(-(a[6] + b1.z)));
    o1.w = 1.0f / (1.0f + __expf(-(a[7] + b1.w)));
    float* op = out + (size_t)row * D_IN + c0;
    *(float4*)(op)     = o0;
    *(float4*)(op + 4) = o1;
}

// ---- shared epilogue ----
template <int EPI>
DINL void gemm_epilogue(float c[2][8][4], int mtile, int ntile, int m0, int n0,
                        int g, int t, const float* bias, float* out_f,
                        __nv_bfloat16* out_h, __nv_bfloat16* out_l, int ldo)
{
#pragma unroll
    for (int i = 0; i < 2; i++) {
        int r0 = mtile * 128 + m0 + i * 16 + g;
#pragma unroll
        for (int j = 0; j < 8; j++) {
            int col = ntile * 128 + n0 + j * 8 + 2 * t;
            float2 bb = *(const float2*)&bias[col];
            float v0 = c[i][j][0] + bb.x, v1 = c[i][j][1] + bb.y;
            float v2 = c[i][j][2] + bb.x, v3 = c[i][j][3] + bb.y;
            if (EPI == 0) {
                v0 = fmaxf(v0, 0.0f); v1 = fmaxf(v1, 0.0f);
                v2 = fmaxf(v2, 0.0f); v3 = fmaxf(v3, 0.0f);
                __nv_bfloat16 h0 = __float2bfloat16(v0), h1 = __float2bfloat16(v1);
                __nv_bfloat16 h2 = __float2bfloat16(v2), h3 = __float2bfloat16(v3);
                *(uint32_t*)&out_h[(size_t)r0 * ldo + col]       = pack_bf2(h0, h1);
                *(uint32_t*)&out_h[(size_t)(r0 + 8) * ldo + col] = pack_bf2(h2, h3);
                *(uint32_t*)&out_l[(size_t)r0 * ldo + col] =
                    pack_bf2(__float2bfloat16(v0 - __bfloat162float(h0)),
                             __float2bfloat16(v1 - __bfloat162float(h1)));
                *(uint32_t*)&out_l[(size_t)(r0 + 8) * ldo + col] =
                    pack_bf2(__float2bfloat16(v2 - __bfloat162float(h2)),
                             __float2bfloat16(v3 - __bfloat162float(h3)));
            } else {
                *(float2*)&out_f[(size_t)r0 * ldo + col]       = make_float2(v0, v1);
                *(float2*)&out_f[(size_t)(r0 + 8) * ldo + col] = make_float2(v2, v3);
            }
        }
    }
}

// ---- TMA split-bf16 GEMM (ntile fast on blockIdx.x for A-tile L2 reuse) ----
template <int EPI>
__global__ void __launch_bounds__(256, 1) gemm_tma(
    const __grid_constant__ CUtensorMap mAh, const __grid_constant__ CUtensorMap mAl,
    const __grid_constant__ CUtensorMap mBh, const __grid_constant__ CUtensorMap mBl,
    const float* __restrict__ bias, int K,
    float* __restrict__ out_f,
    __nv_bfloat16* __restrict__ out_h, __nv_bfloat16* __restrict__ out_l, int ldo)
{
    extern __shared__ __align__(16) char smem[];
    __shared__ __align__(8) uint64_t mbars[6];   // full[0..2], empty[3..5]
    const int tid = threadIdx.x;
    const int wid = tid >> 5, lane = tid & 31;
    const int g = lane >> 2, t = lane & 3;
    const int m4 = lane >> 3, r8 = lane & 7;
    const int m0 = (wid & 3) * 32, n0 = (wid >> 2) * 64;
    const int mtile = blockIdx.y, ntile = blockIdx.x;   // SWAPPED: ntile fast
    const int KT = K / 64;
    const uint32_t base = (smem_u32(smem) + 1023u) & ~1023u;
    const uint32_t mb = smem_u32(mbars);

    float c[2][8][4];
#pragma unroll
    for (int i = 0; i < 2; i++)
#pragma unroll
        for (int j = 0; j < 8; j++)
#pragma unroll
            for (int q = 0; q < 4; q++) c[i][j][q] = 0.0f;

    uint32_t baA[2], xmA[2], baB[4], xmB[4];
    const uint32_t selA = (uint32_t)((m4 >> 1) << 4);
    const uint32_t selB = (uint32_t)((m4 & 1) << 4);
#pragma unroll
    for (int i = 0; i < 2; i++) {
        uint32_t r = (uint32_t)(m0 + i * 16 + ((m4 & 1) << 3) + r8);
        baA[i] = r * 128u;
        xmA[i] = (r & 7u) << 4;
    }
#pragma unroll
    for (int q = 0; q < 4; q++) {
        uint32_t r = (uint32_t)(n0 + (2 * q + (m4 >> 1)) * 8 + r8);
        baB[q] = r * 128u;
        xmB[q] = (r & 7u) << 4;
    }

    if (tid == 0) {
#pragma unroll
        for (int s = 0; s < 3; s++) { mbar_init(mb + 8 * s, 1); mbar_init(mb + 24 + 8 * s, 8); }
    }
    __syncthreads();

    auto issue = [&](int kt) {
        int buf = kt % 3;
        uint32_t sb = base + (uint32_t)buf * TSTAGE;
        uint32_t fb = mb + 8 * buf;
        mbar_expect(fb, TSTAGE);
        tma2d(sb,             &mAh, kt * 64, mtile * 128, fb);
        tma2d(sb + TTILE,     &mAl, kt * 64, mtile * 128, fb);
        tma2d(sb + 2 * TTILE, &mBh, kt * 64, ntile * 128, fb);
        tma2d(sb + 3 * TTILE, &mBl, kt * 64, ntile * 128, fb);
    };

    if (tid == 0) {
        int np = KT < 3 ? KT : 3;
        for (int p = 0; p < np; p++) issue(p);
    }

#pragma unroll 1
    for (int kt = 0; kt < KT; kt++) {
        const int buf = kt % 3;
        const uint32_t ph = (uint32_t)((kt / 3) & 1);
        mbar_wait(mb + 8 * buf, ph);

        const uint32_t sA = base + (uint32_t)buf * TSTAGE;
        const uint32_t sAl = sA + TTILE, sBh = sA + 2 * TTILE, sBl = sA + 3 * TTILE;

#pragma unroll
        for (int kk = 0; kk < 4; kk++) {
            const uint32_t cbA = (uint32_t)(kk * 32) + selA;
            const uint32_t cbB = (uint32_t)(kk * 32) + selB;
            uint32_t ah[2][4], al[2][4], bh[8][2], bl[8][2];
#pragma unroll
            for (int i = 0; i < 2; i++) {
                uint32_t o = baA[i] + (cbA ^ xmA[i]);
                ldsm4(ah[i][0], ah[i][1], ah[i][2], ah[i][3], sA + o);
                ldsm4(al[i][0], al[i][1], al[i][2], al[i][3], sAl + o);
            }
#pragma unroll
            for (int q = 0; q < 4; q++) {
                uint32_t o = baB[q] + (cbB ^ xmB[q]);
                ldsm4(bh[2 * q][0], bh[2 * q][1], bh[2 * q + 1][0], bh[2 * q + 1][1], sBh + o);
                ldsm4(bl[2 * q][0], bl[2 * q][1], bl[2 * q + 1][0], bl[2 * q + 1][1], sBl + o);
            }
#pragma unroll
            for (int i = 0; i < 2; i++)
#pragma unroll
                for (int j = 0; j < 8; j++) {
                    mma_bf16(c[i][j], ah[i][0], ah[i][1], ah[i][2], ah[i][3], bh[j][0], bh[j][1]);
                    mma_bf16(c[i][j], ah[i][0], ah[i][1], ah[i][2], ah[i][3], bl[j][0], bl[j][1]);
                    mma_bf16(c[i][j], al[i][0], al[i][1], al[i][2], al[i][3], bh[j][0], bh[j][1]);
                }
        }

        if (elect_one()) mbar_arrive(mb + 24 + 8 * buf);
        if (tid == 0 && kt + 3 < KT) {
            mbar_wait(mb + 24 + 8 * buf, ph);
            issue(kt + 3);
        }
    }

    gemm_epilogue<EPI>(c, mtile, ntile, m0, n0, g, t, bias, out_f, out_h, out_l, ldo);
}

// ---- fallback cp.async split-bf16 GEMM (ntile fast) ----
template <int EPI>
__global__ void __launch_bounds__(256, 1) gemm_kernel(
    const __nv_bfloat16* __restrict__ Ah, const __nv_bfloat16* __restrict__ Al,
    const __nv_bfloat16* __restrict__ Bh, const __nv_bfloat16* __restrict__ Bl,
    const float* __restrict__ bias, int K,
    float* __restrict__ out_f,
    __nv_bfloat16* __restrict__ out_h, __nv_bfloat16* __restrict__ out_l, int ldo)
{
    extern __shared__ __align__(16) char smem[];
    const int tid = threadIdx.x;
    const int wid = tid >> 5, lane = tid & 31;
    const int g = lane >> 2, t = lane & 3;
    const int m4 = lane >> 3, r8 = lane & 7;
    const int m0 = (wid & 3) * 32, n0 = (wid >> 2) * 64;
    const int mtile = blockIdx.y, ntile = blockIdx.x;   // SWAPPED
    const int KT = K / TKT;
    const __nv_bfloat16* gbase[4] = { Ah, Al, Bh, Bl };

    float c[2][8][4];
#pragma unroll
    for (int i = 0; i < 2; i++)
#pragma unroll
        for (int j = 0; j < 8; j++)
#pragma unroll
            for (int q = 0; q < 4; q++) c[i][j][q] = 0.0f;

    uint32_t offA[2], offB[4];
#pragma unroll
    for (int i = 0; i < 2; i++)
        offA[i] = (uint32_t)(((m0 + i * 16 + ((m4 & 1) << 3) + r8) * SROW
                              + ((m4 >> 1) << 3)) * 2);
#pragma unroll
    for (int q = 0; q < 4; q++)
        offB[q] = (uint32_t)(((n0 + (2 * q + (m4 >> 1)) * 8 + r8) * SROW
                              + ((m4 & 1) << 3)) * 2);

    const uint32_t sb0 = smem_u32(smem);

    auto load_stage = [&](int kt, int buf) {
        char* sb = smem + buf * STAGE_BYTES;
#pragma unroll
        for (int i = 0; i < 16; i++) {
            int id = tid + 256 * i;
            int arr = id >> 10;
            int rem = id & 1023;
            int row = rem >> 3, chunk = rem & 7;
            int grow = ((arr < 2) ? mtile : ntile) * 128 + row;
            const char* src = (const char*)(gbase[arr] + (size_t)grow * K + (size_t)kt * TKT)
                              + chunk * 16;
            uint32_t dst = smem_u32(sb + arr * TILE_BYTES + row * (SROW * 2) + chunk * 16);
            cp16(dst, src);
        }
    };

    load_stage(0, 0);
    cp_commit();
    load_stage(1, 1);
    cp_commit();

#pragma unroll 1
    for (int kt = 0; kt < KT; kt++) {
        if (kt + 1 < KT) cp_wait<1>(); else cp_wait<0>();
        __syncthreads();
        if (kt + 2 < KT) { load_stage(kt + 2, (kt + 2) % NSTAGE); cp_commit(); }

        const uint32_t sA = sb0 + (kt % NSTAGE) * STAGE_BYTES;
        const uint32_t sB = sA + 2 * TILE_BYTES;

#pragma unroll
        for (int kk = 0; kk < 4; kk++) {
            const uint32_t kb = (uint32_t)kk * 32;
            uint32_t ah[2][4], al[2][4], bh[8][2], bl[8][2];
#pragma unroll
            for (int i = 0; i < 2; i++) {
                ldsm4(ah[i][0], ah[i][1], ah[i][2], ah[i][3], sA + offA[i] + kb);
                ldsm4(al[i][0], al[i][1], al[i][2], al[i][3], sA + TILE_BYTES + offA[i] + kb);
            }
#pragma unroll
            for (int q = 0; q < 4; q++) {
                ldsm4(bh[2 * q][0], bh[2 * q][1], bh[2 * q + 1][0], bh[2 * q + 1][1],
                      sB + offB[q] + kb);
                ldsm4(bl[2 * q][0], bl[2 * q][1], bl[2 * q + 1][0], bl[2 * q + 1][1],
                      sB + TILE_BYTES + offB[q] + kb);
            }
#pragma unroll
            for (int i = 0; i < 2; i++)
#pragma unroll
                for (int j = 0; j < 8; j++) {
                    mma_bf16(c[i][j], ah[i][0], ah[i][1], ah[i][2], ah[i][3], bh[j][0], bh[j][1]);
                    mma_bf16(c[i][j], ah[i][0], ah[i][1], ah[i][2], ah[i][3], bl[j][0], bl[j][1]);
                    mma_bf16(c[i][j], al[i][0], al[i][1], al[i][2], al[i][3], bh[j][0], bh[j][1]);
                }
        }
        __syncthreads();
    }

    gemm_epilogue<EPI>(c, mtile, ntile, m0, n0, g, t, bias, out_f, out_h, out_l, ldo);
}

// ---- host ----
template <typename T> static T* sym(const void* s) {
    void* p = nullptr;
    cudaGetSymbolAddress(&p, s);
    return (T*)p;
}

typedef CUresult (*EncFn)(CUtensorMap*, CUtensorMapDataType, cuuint32_t, void*,
                          const cuuint64_t*, const cuuint64_t*, const cuuint32_t*,
                          const cuuint32_t*, CUtensorMapInterleave, CUtensorMapSwizzle,
                          CUtensorMapL2promotion, CUtensorMapFloatOOBfill);

static bool enc2d(EncFn enc, CUtensorMap* m, void* ptr, uint64_t K, uint64_t R) {
    cuuint64_t dims[2] = { K, R };
    cuuint64_t strides[1] = { K * 2 };
    cuuint32_t box[2] = { 64, 128 };
    cuuint32_t es[2] = { 1, 1 };
    return enc(m, CU_TENSOR_MAP_DATA_TYPE_BFLOAT16, 2, ptr, dims, strides, box, es,
               CU_TENSOR_MAP_INTERLEAVE_NONE, CU_TENSOR_MAP_SWIZZLE_128B,
               CU_TENSOR_MAP_L2_PROMOTION_L2_128B,
               CU_TENSOR_MAP_FLOAT_OOB_FILL_NONE) == CUDA_SUCCESS;
}

extern "C" void kernel_launch(void* const* d_in, const int* in_sizes, int n_in,
                              void* d_out, int out_size)
{
    const float* X  = (const float*)d_in[0];
    const float* W1 = (const float*)d_in[1];
    const float* b1 = (const float*)d_in[2];
    const float* W2 = (const float*)d_in[3];
    const float* b2 = (const float*)d_in[4];
    const float* W3 = (const float*)d_in[5];
    const float* b3 = (const float*)d_in[6];
    const int* knb  = (const int*)d_in[7];
    float* out = (float*)d_out;

    __nv_bfloat16* Xh  = sym<__nv_bfloat16>(g_Xh);
    __nv_bfloat16* Xl  = sym<__nv_bfloat16>(g_Xl);
    __nv_bfloat16* W1h = sym<__nv_bfloat16>(g_W1h);
    __nv_bfloat16* W1l = sym<__nv_bfloat16>(g_W1l);
    __nv_bfloat16* W2h = sym<__nv_bfloat16>(g_W2h);
    __nv_bfloat16* W2l = sym<__nv_bfloat16>(g_W2l);
    __half*        W3f = sym<__half>(g_W3f);
    __nv_bfloat16* H1h = sym<__nv_bfloat16>(g_H1h);
    __nv_bfloat16* H1l = sym<__nv_bfloat16>(g_H1l);
    float*         H2  = sym<float>(g_H2);
    float*         gv  = sym<float>(g_sv);
    int*           gi  = sym<int>(g_si);
    int*           gc  = sym<int>(g_sc);

    void* h = dlopen("libcuda.so.1", RTLD_LAZY | RTLD_GLOBAL);
    if (!h) h = dlopen("libcuda.so", RTLD_LAZY | RTLD_GLOBAL);
    EncFn enc = h ? (EncFn)dlsym(h, "cuTensorMapEncodeTiled") : nullptr;
    CUtensorMap mXh, mXl, mW1h, mW1l, mH1h, mH1l, mW2h, mW2l;
    bool tma_ok = (enc != nullptr);
    if (tma_ok) {
        tma_ok = enc2d(enc, &mXh, Xh, D_IN, B_ROWS) && enc2d(enc, &mXl, Xl, D_IN, B_ROWS)
              && enc2d(enc, &mW1h, W1h, D_IN, HID)  && enc2d(enc, &mW1l, W1l, D_IN, HID)
              && enc2d(enc, &mH1h, H1h, HID, B_ROWS) && enc2d(enc, &mH1l, H1l, HID, B_ROWS)
              && enc2d(enc, &mW2h, W2h, HID, HID)   && enc2d(enc, &mW2l, W2l, HID, HID);
    }

    cudaFuncSetAttribute(gemm_tma<0>, cudaFuncAttributeMaxDynamicSharedMemorySize, TSMEM);
    cudaFuncSetAttribute(gemm_tma<1>, cudaFuncAttributeMaxDynamicSharedMemorySize, TSMEM);
    cudaFuncSetAttribute(gemm_kernel<0>, cudaFuncAttributeMaxDynamicSharedMemorySize, SMEM_DYN);
    cudaFuncSetAttribute(gemm_kernel<1>, cudaFuncAttributeMaxDynamicSharedMemorySize, SMEM_DYN);

    // 1. split X; convert W3 -> fp16
    size_t n4 = (size_t)B_ROWS * D_IN / 4;
    split_kernel<<<(unsigned)((n4 + 255) / 256), 256>>>((const float4*)X, (uint2*)Xh, (uint2*)Xl, n4);
    size_t w34 = (size_t)HID * D_IN / 4;
    htrunc_kernel<<<(unsigned)((w34 + 255) / 256), 256>>>((const float4*)W3, (uint2*)W3f, w34);

    // 2. transpose+split W1, W2 -> [N, K] pairs
    dim3 t8(32, 8);
    tsplit_kernel<<<dim3(HID / 32, D_IN / 32), t8>>>(W1, W1h, W1l, D_IN, HID);
    tsplit_kernel<<<dim3(HID / 32, HID / 32), t8>>>(W2, W2h, W2l, HID, HID);

    // 3+4. GEMMs (grid: x = ntile fast, y = mtile slow)
    if (tma_ok) {
        gemm_tma<0><<<dim3(HID / 128, B_ROWS / 128), 256, TSMEM>>>(
            mXh, mXl, mW1h, mW1l, b1, D_IN, nullptr, H1h, H1l, HID);
        gemm_tma<1><<<dim3(HID / 128, B_ROWS / 128), 256, TSMEM>>>(
            mH1h, mH1l, mW2h, mW2l, b2, HID, H2, nullptr, nullptr, HID);
    } else {
        gemm_kernel<0><<<dim3(HID / TNT, B_ROWS / TMT), 256, SMEM_DYN>>>(
            Xh, Xl, W1h, W1l, b1, D_IN, nullptr, H1h, H1l, HID);
        gemm_kernel<1><<<dim3(HID / TNT, B_ROWS / TMT), 256, SMEM_DYN>>>(
            H1h, H1l, W2h, W2l, b2, HID, H2, nullptr, nullptr, HID);
    }

    // 5. top-k -> compacted (val, idx, cnt)
    topk_kernel<<<B_ROWS, 256>>>(H2, knb, gv, gi, gc);

    // 6. sparse layer 3 + sigmoid (fp16 W3)
    sparse_out_kernel<<<dim3(B_ROWS, D_IN / CCH), 256>>>(gv, gi, gc, W3f, b3, out);

    (void)in_sizes; (void)n_in; (void)out_size;
}

// round 14
// speedup vs baseline: 1.1280x; 1.0071x over previous
#include <cuda_runtime.h>
#include <cuda.h>
#include <cuda_bf16.h>
#include <cuda_fp16.h>
#include <cstdint>
#include <cstddef>
#include <dlfcn.h>

#define DINL __device__ __forceinline__

#define B_ROWS 8192
#define D_IN   12288
#define HID    2048
#define NCAP   96
#define CCH    2048

// ---- fallback (cp.async) GEMM tiling ----
#define TMT 128
#define TNT 128
#define TKT 64
#define SROW 72
#define TILE_BYTES (128 * SROW * 2)
#define STAGE_BYTES (4 * TILE_BYTES)
#define NSTAGE 3
#define SMEM_DYN (NSTAGE * STAGE_BYTES)

// ---- TMA GEMM tiling ----
#define TTILE 16384                       // 128 rows x 128 B
#define TSTAGE 65536                      // 4 tiles
#define TSMEM (3 * TSTAGE + 1024)

// ---- scratch ----
static __device__ __nv_bfloat16 g_Xh [(size_t)B_ROWS * D_IN];
static __device__ __nv_bfloat16 g_Xl [(size_t)B_ROWS * D_IN];
static __device__ __nv_bfloat16 g_W1h[(size_t)HID * D_IN];
static __device__ __nv_bfloat16 g_W1l[(size_t)HID * D_IN];
static __device__ __nv_bfloat16 g_W2h[(size_t)HID * HID];
static __device__ __nv_bfloat16 g_W2l[(size_t)HID * HID];
static __device__ __half        g_W3f [(size_t)HID * D_IN];
static __device__ __nv_bfloat16 g_H1h[(size_t)B_ROWS * HID];
static __device__ __nv_bfloat16 g_H1l[(size_t)B_ROWS * HID];
static __device__ float         g_H2 [(size_t)B_ROWS * HID];
static __device__ float         g_sv [(size_t)B_ROWS * NCAP];
static __device__ int           g_si [(size_t)B_ROWS * NCAP];
static __device__ int           g_sc [B_ROWS];

// ---- helpers ----
DINL uint32_t smem_u32(const void* p) {
    uint32_t a;
    asm("{ .reg .u64 t; cvta.to.shared.u64 t, %1; cvt.u32.u64 %0, t; }" : "=r"(a) : "l"(p));
    return a;
}
DINL bool elect_one() {
    uint32_t p;
    asm volatile("{ .reg .pred p; elect.sync _|p, 0xFFFFFFFF; selp.b32 %0, 1, 0, p; }" : "=r"(p));
    return p != 0;
}
DINL void cp16(uint32_t d, const void* s) {
    asm volatile("cp.async.cg.shared.global [%0], [%1], 16;" :: "r"(d), "l"(s));
}
DINL void cp_commit() { asm volatile("cp.async.commit_group;" ::: "memory"); }
template <int N> DINL void cp_wait() {
    asm volatile("cp.async.wait_group %0;" :: "n"(N) : "memory");
}
DINL void ldsm4(uint32_t& r0, uint32_t& r1, uint32_t& r2, uint32_t& r3, uint32_t addr) {
    asm volatile("ldmatrix.sync.aligned.m8n8.x4.shared.b16 {%0,%1,%2,%3}, [%4];"
                 : "=r"(r0), "=r"(r1), "=r"(r2), "=r"(r3) : "r"(addr));
}
DINL void mma_bf16(float* c, uint32_t a0, uint32_t a1, uint32_t a2, uint32_t a3,
                   uint32_t b0, uint32_t b1) {
    asm volatile(
        "mma.sync.aligned.m16n8k16.row.col.f32.bf16.bf16.f32 "
        "{%0,%1,%2,%3},{%4,%5,%6,%7},{%8,%9},{%0,%1,%2,%3};"
        : "+f"(c[0]), "+f"(c[1]), "+f"(c[2]), "+f"(c[3])
        : "r"(a0), "r"(a1), "r"(a2), "r"(a3), "r"(b0), "r"(b1));
}
DINL uint32_t pack_bf2(__nv_bfloat16 a, __nv_bfloat16 b) {
    return (uint32_t)__bfloat16_as_ushort(a) | ((uint32_t)__bfloat16_as_ushort(b) << 16);
}
DINL void mbar_init(uint32_t a, uint32_t c) {
    asm volatile("mbarrier.init.shared.b64 [%0], %1;" :: "r"(a), "r"(c) : "memory");
}
DINL void mbar_arrive(uint32_t a) {
    asm volatile("mbarrier.arrive.shared.b64 _, [%0];" :: "r"(a) : "memory");
}
DINL void mbar_expect(uint32_t a, uint32_t bytes) {
    asm volatile("mbarrier.arrive.expect_tx.shared.b64 _, [%0], %1;"
                 :: "r"(a), "r"(bytes) : "memory");
}
DINL void mbar_wait(uint32_t a, uint32_t par) {
    asm volatile(
        "{\n\t.reg .pred P;\n\t"
        "WL%=:\n\t"
        "mbarrier.try_wait.parity.acquire.cta.shared::cta.b64 P, [%0], %1, 0x989680;\n\t"
        "@P bra WD%=;\n\t"
        "bra WL%=;\n\t"
        "WD%=:\n\t}"
        :: "r"(a), "r"(par) : "memory");
}
DINL void tma2d(uint32_t dst, const void* map, int cx, int cy, uint32_t mbar) {
    asm volatile(
        "cp.async.bulk.tensor.2d.shared::cta.global.tile.mbarrier::complete_tx::bytes "
        "[%0], [%1, {%2, %3}], [%4];"
        :: "r"(dst), "l"(map), "r"(cx), "r"(cy), "r"(mbar) : "memory");
}

// ---- split X (2 float4 per thread for MLP) ----
__global__ void __launch_bounds__(256) split_kernel(
    const float4* __restrict__ src, uint2* __restrict__ dh, uint2* __restrict__ dl, size_t n4)
{
    size_t i0 = (size_t)blockIdx.x * 512u + threadIdx.x;
#pragma unroll
    for (int r = 0; r < 2; r++) {
        size_t i = i0 + (size_t)r * 256u;
        if (i >= n4) break;
        float4 x = src[i];
        __nv_bfloat16 h0 = __float2bfloat16(x.x), h1 = __float2bfloat16(x.y);
        __nv_bfloat16 h2 = __float2bfloat16(x.z), h3 = __float2bfloat16(x.w);
        dh[i] = make_uint2(pack_bf2(h0, h1), pack_bf2(h2, h3));
        dl[i] = make_uint2(
            pack_bf2(__float2bfloat16(x.x - __bfloat162float(h0)),
                     __float2bfloat16(x.y - __bfloat162float(h1))),
            pack_bf2(__float2bfloat16(x.z - __bfloat162float(h2)),
                     __float2bfloat16(x.w - __bfloat162float(h3))));
    }
}

// ---- transpose + split weights ----
__global__ void __launch_bounds__(256) tsplit_kernel(
    const float* __restrict__ src, __nv_bfloat16* __restrict__ dh,
    __nv_bfloat16* __restrict__ dl, int R, int C)
{
    __shared__ float tile[32][33];
    int c0 = blockIdx.x * 32, r0 = blockIdx.y * 32;
    int tx = threadIdx.x, ty = threadIdx.y;
#pragma unroll
    for (int j = 0; j < 32; j += 8)
        tile[ty + j][tx] = src[(size_t)(r0 + ty + j) * C + (c0 + tx)];
    __syncthreads();
#pragma unroll
    for (int j = 0; j < 32; j += 8) {
        float v = tile[tx][ty + j];
        size_t o = (size_t)(c0 + ty + j) * R + (r0 + tx);
        __nv_bfloat16 h = __float2bfloat16(v);
        dh[o] = h;
        dl[o] = __float2bfloat16(v - __bfloat162float(h));
    }
}

// ---- W3 f32 -> fp16 ----
__global__ void __launch_bounds__(256) htrunc_kernel(
    const float4* __restrict__ src, uint2* __restrict__ dst, size_t n4)
{
    size_t i = (size_t)blockIdx.x * 256u + threadIdx.x;
    if (i >= n4) return;
    float4 x = src[i];
    __half2 lo = __floats2half2_rn(x.x, x.y);
    __half2 hi = __floats2half2_rn(x.z, x.w);
    dst[i] = make_uint2(*(uint32_t*)&lo, *(uint32_t*)&hi);
}

// ---- exact top-k threshold + deterministic compaction ----
DINL unsigned fmap(float x) {
    unsigned b = __float_as_uint(x);
    return (b & 0x80000000u) ? ~b : (b | 0x80000000u);
}
__global__ void __launch_bounds__(256) topk_kernel(
    const float* __restrict__ H2, const int* __restrict__ knb,
    float* __restrict__ gv, int* __restrict__ gi, int* __restrict__ gc)
{
    __shared__ int hist[256];
    __shared__ unsigned sh_pref;
    __shared__ int sh_k;
    __shared__ float s_val[NCAP];
    __shared__ int s_idx[NCAP];
    __shared__ int wsum[8];
    __shared__ int s_tot;
    const int row = blockIdx.x, t = threadIdx.x;
    const int lane = t & 31, w = t >> 5;
    const float* rp = H2 + (size_t)row * HID;
    float v[8]; unsigned u[8];
#pragma unroll
    for (int j = 0; j < 8; j++) { v[j] = rp[t + 256 * j]; u[j] = fmap(v[j]); }
    int k = *knb;
    unsigned prefix = 0, mask = 0;
#pragma unroll 1
    for (int by = 3; by >= 0; by--) {
        hist[t] = 0;
        __syncthreads();
#pragma unroll
        for (int j = 0; j < 8; j++)
            if ((u[j] & mask) == prefix)
                atomicAdd(&hist[(u[j] >> (by * 8)) & 255], 1);
        __syncthreads();
        if (t == 0) {
            int cum = 0, d = 255;
            for (; d > 0; d--) { cum += hist[d]; if (cum >= k) break; }
            if (cum < k) cum += hist[0];
            sh_pref = prefix | ((unsigned)d << (by * 8));
            sh_k = k - (cum - hist[d]);
        }
        __syncthreads();
        prefix = sh_pref; k = sh_k;
        mask |= (0xFFu << (by * 8));
        __syncthreads();
    }
    const unsigned th = prefix;

    int n = 0;
    bool act[8];
#pragma unroll
    for (int j = 0; j < 8; j++) { act[j] = (u[j] >= th); n += act[j] ? 1 : 0; }
    int incl = n;
#pragma unroll
    for (int o = 1; o < 32; o <<= 1) {
        int y = __shfl_up_sync(0xFFFFFFFFu, incl, o);
        if (lane >= o) incl += y;
    }
    if (lane == 31) wsum[w] = incl;
    __syncthreads();
    if (t == 0) {
        int a = 0;
#pragma unroll
        for (int i = 0; i < 8; i++) { int b = wsum[i]; wsum[i] = a; a += b; }
        s_tot = (a > NCAP) ? NCAP : a;
    }
    __syncthreads();
    int pos = wsum[w] + incl - n;
#pragma unroll
    for (int j = 0; j < 8; j++) {
        if (act[j] && pos < NCAP) { s_val[pos] = v[j]; s_idx[pos] = t + 256 * j; pos++; }
    }
    __syncthreads();
    int tot = s_tot;
    if (t < NCAP) {
        gv[(size_t)row * NCAP + t] = (t < tot) ? s_val[t] : 0.0f;
        gi[(size_t)row * NCAP + t] = (t < tot) ? s_idx[t] : 0;
    }
    if (t == 0) gc[row] = tot;
}

// ---- sparse layer 3 (fp16 W3, one uint4 load per k) ----
__global__ void __launch_bounds__(256) sparse_out_kernel(
    const float* __restrict__ gv, const int* __restrict__ gi, const int* __restrict__ gc,
    const __half* __restrict__ W3, const float* __restrict__ b3, float* __restrict__ out)
{
    __shared__ float sv[NCAP];
    __shared__ int si[NCAP];
    const int row = blockIdx.x, ch = blockIdx.y, t = threadIdx.x;
    if (t < NCAP) {
        sv[t] = gv[(size_t)row * NCAP + t];
        si[t] = gi[(size_t)row * NCAP + t];
    }
    __syncthreads();
    const int cnt = gc[row];
    const int c0 = ch * CCH + 8 * t;

    float a[8] = {0, 0, 0, 0, 0, 0, 0, 0};
#pragma unroll 2
    for (int k = 0; k < cnt; k++) {
        float vv = sv[k];
        uint4 q = *(const uint4*)(W3 + (size_t)si[k] * D_IN + c0);
        float2 p;
        p = __half22float2(*(__half2*)&q.x); a[0] += vv * p.x; a[1] += vv * p.y;
        p = __half22float2(*(__half2*)&q.y); a[2] += vv * p.x; a[3] += vv * p.y;
        p = __half22float2(*(__half2*)&q.z); a[4] += vv * p.x; a[5] += vv * p.y;
        p = __half22float2(*(__half2*)&q.w); a[6] += vv * p.x; a[7] += vv * p.y;
    }
    float4 b0 = *(const float4*)(b3 + c0);
    float4 b1 = *(const float4*)(b3 + c0 + 4);
    float4 o0, o1;
    o0.x = 1.0f / (1.0f + __expf(-(a[0] + b0.x)));
    o0.y = 1.0f / (1.0f + __expf(-(a[1] + b0.y)));
    o0.z = 1.0f / (1.0f + __expf(-(a[2] + b0.z)));
    o0.w = 1.0f / (1.0f + __expf(-(a[3] + b0.w)));
    o1.x = 1.0f / (1.0f + __expf(-(a[4] + b1.x)));
    o1.y = 1.0f / (1.0f + __expf(-(a[5] + b1.y)));
    o1.z = 1.0f / (1.0f + __expf(-(a[6] + b1.z)));
    o1.w = 1.0f / (1.0f + __expf(-(a[7] + b1.w)));
    float* op = out + (size_t)row * D_IN + c0;
    *(float4*)(op)     = o0;
    *(float4*)(op + 4) = o1;
}

// ---- shared epilogue ----
template <int EPI>
DINL void gemm_epilogue(float c[2][8][4], int mtile, int ntile, int m0, int n0,
                        int g, int t, const float* bias, float* out_f,
                        __nv_bfloat16* out_h, __nv_bfloat16* out_l, int ldo)
{
#pragma unroll
    for (int i = 0; i < 2; i++) {
        int r0 = mtile * 128 + m0 + i * 16 + g;
#pragma unroll
        for (int j = 0; j < 8; j++) {
            int col = ntile * 128 + n0 + j * 8 + 2 * t;
            float2 bb = *(const float2*)&bias[col];
            float v0 = c[i][j][0] + bb.x, v1 = c[i][j][1] + bb.y;
            float v2 = c[i][j][2] + bb.x, v3 = c[i][j][3] + bb.y;
            if (EPI == 0) {
                v0 = fmaxf(v0, 0.0f); v1 = fmaxf(v1, 0.0f);
                v2 = fmaxf(v2, 0.0f); v3 = fmaxf(v3, 0.0f);
                __nv_bfloat16 h0 = __float2bfloat16(v0), h1 = __float2bfloat16(v1);
                __nv_bfloat16 h2 = __float2bfloat16(v2), h3 = __float2bfloat16(v3);
                *(uint32_t*)&out_h[(size_t)r0 * ldo + col]       = pack_bf2(h0, h1);
                *(uint32_t*)&out_h[(size_t)(r0 + 8) * ldo + col] = pack_bf2(h2, h3);
                *(uint32_t*)&out_l[(size_t)r0 * ldo + col] =
                    pack_bf2(__float2bfloat16(v0 - __bfloat162float(h0)),
                             __float2bfloat16(v1 - __bfloat162float(h1)));
                *(uint32_t*)&out_l[(size_t)(r0 + 8) * ldo + col] =
                    pack_bf2(__float2bfloat16(v2 - __bfloat162float(h2)),
                             __float2bfloat16(v3 - __bfloat162float(h3)));
            } else {
                *(float2*)&out_f[(size_t)r0 * ldo + col]       = make_float2(v0, v1);
                *(float2*)&out_f[(size_t)(r0 + 8) * ldo + col] = make_float2(v2, v3);
            }
        }
    }
}

// ---- TMA split-bf16 GEMM (early empty-arrive after final LDSM of each stage) ----
template <int EPI>
__global__ void __launch_bounds__(256, 1) gemm_tma(
    const __grid_constant__ CUtensorMap mAh, const __grid_constant__ CUtensorMap mAl,
    const __grid_constant__ CUtensorMap mBh, const __grid_constant__ CUtensorMap mBl,
    const float* __restrict__ bias, int K,
    float* __restrict__ out_f,
    __nv_bfloat16* __restrict__ out_h, __nv_bfloat16* __restrict__ out_l, int ldo)
{
    extern __shared__ __align__(16) char smem[];
    __shared__ __align__(8) uint64_t mbars[6];   // full[0..2], empty[3..5]
    const int tid = threadIdx.x;
    const int wid = tid >> 5, lane = tid & 31;
    const int g = lane >> 2, t = lane & 3;
    const int m4 = lane >> 3, r8 = lane & 7;
    const int m0 = (wid & 3) * 32, n0 = (wid >> 2) * 64;
    const int mtile = blockIdx.y, ntile = blockIdx.x;
    const int KT = K / 64;
    const uint32_t base = (smem_u32(smem) + 1023u) & ~1023u;
    const uint32_t mb = smem_u32(mbars);

    float c[2][8][4];
#pragma unroll
    for (int i = 0; i < 2; i++)
#pragma unroll
        for (int j = 0; j < 8; j++)
#pragma unroll
            for (int q = 0; q < 4; q++) c[i][j][q] = 0.0f;

    uint32_t baA[2], xmA[2], baB[4], xmB[4];
    const uint32_t selA = (uint32_t)((m4 >> 1) << 4);
    const uint32_t selB = (uint32_t)((m4 & 1) << 4);
#pragma unroll
    for (int i = 0; i < 2; i++) {
        uint32_t r = (uint32_t)(m0 + i * 16 + ((m4 & 1) << 3) + r8);
        baA[i] = r * 128u;
        xmA[i] = (r & 7u) << 4;
    }
#pragma unroll
    for (int q = 0; q < 4; q++) {
        uint32_t r = (uint32_t)(n0 + (2 * q + (m4 >> 1)) * 8 + r8);
        baB[q] = r * 128u;
        xmB[q] = (r & 7u) << 4;
    }

    if (tid == 0) {
#pragma unroll
        for (int s = 0; s < 3; s++) { mbar_init(mb + 8 * s, 1); mbar_init(mb + 24 + 8 * s, 8); }
    }
    __syncthreads();

    auto issue = [&](int kt) {
        int buf = kt % 3;
        uint32_t sb = base + (uint32_t)buf * TSTAGE;
        uint32_t fb = mb + 8 * buf;
        mbar_expect(fb, TSTAGE);
        tma2d(sb,             &mAh, kt * 64, mtile * 128, fb);
        tma2d(sb + TTILE,     &mAl, kt * 64, mtile * 128, fb);
        tma2d(sb + 2 * TTILE, &mBh, kt * 64, ntile * 128, fb);
        tma2d(sb + 3 * TTILE, &mBl, kt * 64, ntile * 128, fb);
    };

    if (tid == 0) {
        int np = KT < 3 ? KT : 3;
        for (int p = 0; p < np; p++) issue(p);
    }

#pragma unroll 1
    for (int kt = 0; kt < KT; kt++) {
        const int buf = kt % 3;
        const uint32_t ph = (uint32_t)((kt / 3) & 1);
        mbar_wait(mb + 8 * buf, ph);

        const uint32_t sA = base + (uint32_t)buf * TSTAGE;
        const uint32_t sAl = sA + TTILE, sBh = sA + 2 * TTILE, sBl = sA + 3 * TTILE;

#pragma unroll
        for (int kk = 0; kk < 4; kk++) {
            const uint32_t cbA = (uint32_t)(kk * 32) + selA;
            const uint32_t cbB = (uint32_t)(kk * 32) + selB;
            uint32_t ah[2][4], al[2][4], bh[8][2], bl[8][2];
#pragma unroll
            for (int i = 0; i < 2; i++) {
                uint32_t o = baA[i] + (cbA ^ xmA[i]);
                ldsm4(ah[i][0], ah[i][1], ah[i][2], ah[i][3], sA + o);
                ldsm4(al[i][0], al[i][1], al[i][2], al[i][3], sAl + o);
            }
#pragma unroll
            for (int q = 0; q < 4; q++) {
                uint32_t o = baB[q] + (cbB ^ xmB[q]);
                ldsm4(bh[2 * q][0], bh[2 * q][1], bh[2 * q + 1][0], bh[2 * q + 1][1], sBh + o);
                ldsm4(bl[2 * q][0], bl[2 * q][1], bl[2 * q + 1][0], bl[2 * q + 1][1], sBl + o);
            }
            // all smem reads for this stage are done once the last kk's LDSMs retire:
            // signal 'empty' BEFORE the final MMA batch so the producer can refill earlier
            if (kk == 3 && elect_one()) mbar_arrive(mb + 24 + 8 * buf);
#pragma unroll
            for (int i = 0; i < 2; i++)
#pragma unroll
                for (int j = 0; j < 8; j++) {
                    mma_bf16(c[i][j], ah[i][0], ah[i][1], ah[i][2], ah[i][3], bh[j][0], bh[j][1]);
                    mma_bf16(c[i][j], ah[i][0], ah[i][1], ah[i][2], ah[i][3], bl[j][0], bl[j][1]);
                    mma_bf16(c[i][j], al[i][0], al[i][1], al[i][2], al[i][3], bh[j][0], bh[j][1]);
                }
        }

        if (tid == 0 && kt + 3 < KT) {
            mbar_wait(mb + 24 + 8 * buf, ph);
            issue(kt + 3);
        }
    }

    gemm_epilogue<EPI>(c, mtile, ntile, m0, n0, g, t, bias, out_f, out_h, out_l, ldo);
}

// ---- fallback cp.async split-bf16 GEMM ----
template <int EPI>
__global__ void __launch_bounds__(256, 1) gemm_kernel(
    const __nv_bfloat16* __restrict__ Ah, const __nv_bfloat16* __restrict__ Al,
    const __nv_bfloat16* __restrict__ Bh, const __nv_bfloat16* __restrict__ Bl,
    const float* __restrict__ bias, int K,
    float* __restrict__ out_f,
    __nv_bfloat16* __restrict__ out_h, __nv_bfloat16* __restrict__ out_l, int ldo)
{
    extern __shared__ __align__(16) char smem[];
    const int tid = threadIdx.x;
    const int wid = tid >> 5, lane = tid & 31;
    const int g = lane >> 2, t = lane & 3;
    const int m4 = lane >> 3, r8 = lane & 7;
    const int m0 = (wid & 3) * 32, n0 = (wid >> 2) * 64;
    const int mtile = blockIdx.y, ntile = blockIdx.x;
    const int KT = K / TKT;
    const __nv_bfloat16* gbase[4] = { Ah, Al, Bh, Bl };

    float c[2][8][4];
#pragma unroll
    for (int i = 0; i < 2; i++)
#pragma unroll
        for (int j = 0; j < 8; j++)
#pragma unroll
            for (int q = 0; q < 4; q++) c[i][j][q] = 0.0f;

    uint32_t offA[2], offB[4];
#pragma unroll
    for (int i = 0; i < 2; i++)
        offA[i] = (uint32_t)(((m0 + i * 16 + ((m4 & 1) << 3) + r8) * SROW
                              + ((m4 >> 1) << 3)) * 2);
#pragma unroll
    for (int q = 0; q < 4; q++)
        offB[q] = (uint32_t)(((n0 + (2 * q + (m4 >> 1)) * 8 + r8) * SROW
                              + ((m4 & 1) << 3)) * 2);

    const uint32_t sb0 = smem_u32(smem);

    auto load_stage = [&](int kt, int buf) {
        char* sb = smem + buf * STAGE_BYTES;
#pragma unroll
        for (int i = 0; i < 16; i++) {
            int id = tid + 256 * i;
            int arr = id >> 10;
            int rem = id & 1023;
            int row = rem >> 3, chunk = rem & 7;
            int grow = ((arr < 2) ? mtile : ntile) * 128 + row;
            const char* src = (const char*)(gbase[arr] + (size_t)grow * K + (size_t)kt * TKT)
                              + chunk * 16;
            uint32_t dst = smem_u32(sb + arr * TILE_BYTES + row * (SROW * 2) + chunk * 16);
            cp16(dst, src);
        }
    };

    load_stage(0, 0);
    cp_commit();
    load_stage(1, 1);
    cp_commit();

#pragma unroll 1
    for (int kt = 0; kt < KT; kt++) {
        if (kt + 1 < KT) cp_wait<1>(); else cp_wait<0>();
        __syncthreads();
        if (kt + 2 < KT) { load_stage(kt + 2, (kt + 2) % NSTAGE); cp_commit(); }

        const uint32_t sA = sb0 + (kt % NSTAGE) * STAGE_BYTES;
        const uint32_t sB = sA + 2 * TILE_BYTES;

#pragma unroll
        for (int kk = 0; kk < 4; kk++) {
            const uint32_t kb = (uint32_t)kk * 32;
            uint32_t ah[2][4], al[2][4], bh[8][2], bl[8][2];
#pragma unroll
            for (int i = 0; i < 2; i++) {
                ldsm4(ah[i][0], ah[i][1], ah[i][2], ah[i][3], sA + offA[i] + kb);
                ldsm4(al[i][0], al[i][1], al[i][2], al[i][3], sA + TILE_BYTES + offA[i] + kb);
            }
#pragma unroll
            for (int q = 0; q < 4; q++) {
                ldsm4(bh[2 * q][0], bh[2 * q][1], bh[2 * q + 1][0], bh[2 * q + 1][1],
                      sB + offB[q] + kb);
                ldsm4(bl[2 * q][0], bl[2 * q][1], bl[2 * q + 1][0], bl[2 * q + 1][1],
                      sB + TILE_BYTES + offB[q] + kb);
            }
#pragma unroll
            for (int i = 0; i < 2; i++)
#pragma unroll
                for (int j = 0; j < 8; j++) {
                    mma_bf16(c[i][j], ah[i][0], ah[i][1], ah[i][2], ah[i][3], bh[j][0], bh[j][1]);
                    mma_bf16(c[i][j], ah[i][0], ah[i][1], ah[i][2], ah[i][3], bl[j][0], bl[j][1]);
                    mma_bf16(c[i][j], al[i][0], al[i][1], al[i][2], al[i][3], bh[j][0], bh[j][1]);
                }
        }
        __syncthreads();
    }

    gemm_epilogue<EPI>(c, mtile, ntile, m0, n0, g, t, bias, out_f, out_h, out_l, ldo);
}

// ---- host ----
template <typename T> static T* sym(const void* s) {
    void* p = nullptr;
    cudaGetSymbolAddress(&p, s);
    return (T*)p;
}

typedef CUresult (*EncFn)(CUtensorMap*, CUtensorMapDataType, cuuint32_t, void*,
                          const cuuint64_t*, const cuuint64_t*, const cuuint32_t*,
                          const cuuint32_t*, CUtensorMapInterleave, CUtensorMapSwizzle,
                          CUtensorMapL2promotion, CUtensorMapFloatOOBfill);

static bool enc2d(EncFn enc, CUtensorMap* m, void* ptr, uint64_t K, uint64_t R) {
    cuuint64_t dims[2] = { K, R };
    cuuint64_t strides[1] = { K * 2 };
    cuuint32_t box[2] = { 64, 128 };
    cuuint32_t es[2] = { 1, 1 };
    return enc(m, CU_TENSOR_MAP_DATA_TYPE_BFLOAT16, 2, ptr, dims, strides, box, es,
               CU_TENSOR_MAP_INTERLEAVE_NONE, CU_TENSOR_MAP_SWIZZLE_128B,
               CU_TENSOR_MAP_L2_PROMOTION_L2_128B,
               CU_TENSOR_MAP_FLOAT_OOB_FILL_NONE) == CUDA_SUCCESS;
}

extern "C" void kernel_launch(void* const* d_in, const int* in_sizes, int n_in,
                              void* d_out, int out_size)
{
    const float* X  = (const float*)d_in[0];
    const float* W1 = (const float*)d_in[1];
    const float* b1 = (const float*)d_in[2];
    const float* W2 = (const float*)d_in[3];
    const float* b2 = (const float*)d_in[4];
    const float* W3 = (const float*)d_in[5];
    const float* b3 = (const float*)d_in[6];
    const int* knb  = (const int*)d_in[7];
    float* out = (float*)d_out;

    __nv_bfloat16* Xh  = sym<__nv_bfloat16>(g_Xh);
    __nv_bfloat16* Xl  = sym<__nv_bfloat16>(g_Xl);
    __nv_bfloat16* W1h = sym<__nv_bfloat16>(g_W1h);
    __nv_bfloat16* W1l = sym<__nv_bfloat16>(g_W1l);
    __nv_bfloat16* W2h = sym<__nv_bfloat16>(g_W2h);
    __nv_bfloat16* W2l = sym<__nv_bfloat16>(g_W2l);
    __half*        W3f = sym<__half>(g_W3f);
    __nv_bfloat16* H1h = sym<__nv_bfloat16>(g_H1h);
    __nv_bfloat16* H1l = sym<__nv_bfloat16>(g_H1l);
    float*         H2  = sym<float>(g_H2);
    float*         gv  = sym<float>(g_sv);
    int*           gi  = sym<int>(g_si);
    int*           gc  = sym<int>(g_sc);

    void* h = dlopen("libcuda.so.1", RTLD_LAZY | RTLD_GLOBAL);
    if (!h) h = dlopen("libcuda.so", RTLD_LAZY | RTLD_GLOBAL);
    EncFn enc = h ? (EncFn)dlsym(h, "cuTensorMapEncodeTiled") : nullptr;
    CUtensorMap mXh, mXl, mW1h, mW1l, mH1h, mH1l, mW2h, mW2l;
    bool tma_ok = (enc != nullptr);
    if (tma_ok) {
        tma_ok = enc2d(enc, &mXh, Xh, D_IN, B_ROWS) && enc2d(enc, &mXl, Xl, D_IN, B_ROWS)
              && enc2d(enc, &mW1h, W1h, D_IN, HID)  && enc2d(enc, &mW1l, W1l, D_IN, HID)
              && enc2d(enc, &mH1h, H1h, HID, B_ROWS) && enc2d(enc, &mH1l, H1l, HID, B_ROWS)
              && enc2d(enc, &mW2h, W2h, HID, HID)   && enc2d(enc, &mW2l, W2l, HID, HID);
    }

    cudaFuncSetAttribute(gemm_tma<0>, cudaFuncAttributeMaxDynamicSharedMemorySize, TSMEM);
    cudaFuncSetAttribute(gemm_tma<1>, cudaFuncAttributeMaxDynamicSharedMemorySize, TSMEM);
    cudaFuncSetAttribute(gemm_kernel<0>, cudaFuncAttributeMaxDynamicSharedMemorySize, SMEM_DYN);
    cudaFuncSetAttribute(gemm_kernel<1>, cudaFuncAttributeMaxDynamicSharedMemorySize, SMEM_DYN);

    // 1. split X; convert W3 -> fp16
    size_t n4 = (size_t)B_ROWS * D_IN / 4;
    split_kernel<<<(unsigned)((n4 + 511) / 512), 256>>>((const float4*)X, (uint2*)Xh, (uint2*)Xl, n4);
    size_t w34 = (size_t)HID * D_IN / 4;
    htrunc_kernel<<<(unsigned)((w34 + 255) / 256), 256>>>((const float4*)W3, (uint2*)W3f, w34);

    // 2. transpose+split W1, W2 -> [N, K] pairs
    dim3 t8(32, 8);
    tsplit_kernel<<<dim3(HID / 32, D_IN / 32), t8>>>(W1, W1h, W1l, D_IN, HID);
    tsplit_kernel<<<dim3(HID / 32, HID / 32), t8>>>(W2, W2h, W2l, HID, HID);

    // 3+4. GEMMs (grid: x = ntile fast, y = mtile slow)
    if (tma_ok) {
        gemm_tma<0><<<dim3(HID / 128, B_ROWS / 128), 256, TSMEM>>>(
            mXh, mXl, mW1h, mW1l, b1, D_IN, nullptr, H1h, H1l, HID);
        gemm_tma<1><<<dim3(HID / 128, B_ROWS / 128), 256, TSMEM>>>(
            mH1h, mH1l, mW2h, mW2l, b2, HID, H2, nullptr, nullptr, HID);
    } else {
        gemm_kernel<0><<<dim3(HID / TNT, B_ROWS / TMT), 256, SMEM_DYN>>>(
            Xh, Xl, W1h, W1l, b1, D_IN, nullptr, H1h, H1l, HID);
        gemm_kernel<1><<<dim3(HID / TNT, B_ROWS / TMT), 256, SMEM_DYN>>>(
            H1h, H1l, W2h, W2l, b2, HID, H2, nullptr, nullptr, HID);
    }

    // 5. top-k -> compacted (val, idx, cnt)
    topk_kernel<<<B_ROWS, 256>>>(H2, knb, gv, gi, gc);

    // 6. sparse layer 3 + sigmoid (fp16 W3)
    sparse_out_kernel<<<dim3(B_ROWS, D_IN / CCH), 256>>>(gv, gi, gc, W3f, b3, out);

    (void)in_sizes; (void)n_in; (void)out_size;
}

// round 15
// speedup vs baseline: 1.1286x; 1.0006x over previous
#include <cuda_runtime.h>
#include <cuda.h>
#include <cuda_bf16.h>
#include <cuda_fp16.h>
#include <cstdint>
#include <cstddef>
#include <dlfcn.h>

#define DINL __device__ __forceinline__

#define B_ROWS 8192
#define D_IN   12288
#define HID    2048
#define NCAP   96
#define CCH    2048

// ---- fallback (cp.async) GEMM tiling ----
#define TMT 128
#define TNT 128
#define TKT 64
#define SROW 72
#define TILE_BYTES (128 * SROW * 2)
#define STAGE_BYTES (4 * TILE_BYTES)
#define NSTAGE 3
#define SMEM_DYN (NSTAGE * STAGE_BYTES)

// ---- TMA GEMM tiling ----
#define TTILE 16384                       // 128 rows x 128 B
#define TSTAGE 65536                      // 4 tiles
#define TSMEM (3 * TSTAGE + 1024)

// ---- scratch ----
static __device__ __nv_bfloat16 g_Xh [(size_t)B_ROWS * D_IN];
static __device__ __nv_bfloat16 g_Xl [(size_t)B_ROWS * D_IN];
static __device__ __nv_bfloat16 g_W1h[(size_t)HID * D_IN];
static __device__ __nv_bfloat16 g_W1l[(size_t)HID * D_IN];
static __device__ __nv_bfloat16 g_W2h[(size_t)HID * HID];
static __device__ __nv_bfloat16 g_W2l[(size_t)HID * HID];
static __device__ __half        g_W3f [(size_t)HID * D_IN];
static __device__ __nv_bfloat16 g_H1h[(size_t)B_ROWS * HID];
static __device__ __nv_bfloat16 g_H1l[(size_t)B_ROWS * HID];
static __device__ float         g_H2 [(size_t)B_ROWS * HID];
static __device__ float         g_sv [(size_t)B_ROWS * NCAP];
static __device__ int           g_si [(size_t)B_ROWS * NCAP];
static __device__ int           g_sc [B_ROWS];

// ---- helpers ----
DINL uint32_t smem_u32(const void* p) {
    uint32_t a;
    asm("{ .reg .u64 t; cvta.to.shared.u64 t, %1; cvt.u32.u64 %0, t; }" : "=r"(a) : "l"(p));
    return a;
}
DINL bool elect_one() {
    uint32_t p;
    asm volatile("{ .reg .pred p; elect.sync _|p, 0xFFFFFFFF; selp.b32 %0, 1, 0, p; }" : "=r"(p));
    return p != 0;
}
DINL void cp16(uint32_t d, const void* s) {
    asm volatile("cp.async.cg.shared.global [%0], [%1], 16;" :: "r"(d), "l"(s));
}
DINL void cp_commit() { asm volatile("cp.async.commit_group;" ::: "memory"); }
template <int N> DINL void cp_wait() {
    asm volatile("cp.async.wait_group %0;" :: "n"(N) : "memory");
}
DINL void ldsm4(uint32_t& r0, uint32_t& r1, uint32_t& r2, uint32_t& r3, uint32_t addr) {
    asm volatile("ldmatrix.sync.aligned.m8n8.x4.shared.b16 {%0,%1,%2,%3}, [%4];"
                 : "=r"(r0), "=r"(r1), "=r"(r2), "=r"(r3) : "r"(addr));
}
DINL void mma_bf16(float* c, uint32_t a0, uint32_t a1, uint32_t a2, uint32_t a3,
                   uint32_t b0, uint32_t b1) {
    asm volatile(
        "mma.sync.aligned.m16n8k16.row.col.f32.bf16.bf16.f32 "
        "{%0,%1,%2,%3},{%4,%5,%6,%7},{%8,%9},{%0,%1,%2,%3};"
        : "+f"(c[0]), "+f"(c[1]), "+f"(c[2]), "+f"(c[3])
        : "r"(a0), "r"(a1), "r"(a2), "r"(a3), "r"(b0), "r"(b1));
}
DINL uint32_t pack_bf2(__nv_bfloat16 a, __nv_bfloat16 b) {
    return (uint32_t)__bfloat16_as_ushort(a) | ((uint32_t)__bfloat16_as_ushort(b) << 16);
}
DINL void mbar_init(uint32_t a, uint32_t c) {
    asm volatile("mbarrier.init.shared.b64 [%0], %1;" :: "r"(a), "r"(c) : "memory");
}
DINL void mbar_arrive(uint32_t a) {
    asm volatile("mbarrier.arrive.shared.b64 _, [%0];" :: "r"(a) : "memory");
}
DINL void mbar_expect(uint32_t a, uint32_t bytes) {
    asm volatile("mbarrier.arrive.expect_tx.shared.b64 _, [%0], %1;"
                 :: "r"(a), "r"(bytes) : "memory");
}
DINL void mbar_wait(uint32_t a, uint32_t par) {
    asm volatile(
        "{\n\t.reg .pred P;\n\t"
        "WL%=:\n\t"
        "mbarrier.try_wait.parity.acquire.cta.shared::cta.b64 P, [%0], %1, 0x989680;\n\t"
        "@P bra WD%=;\n\t"
        "bra WL%=;\n\t"
        "WD%=:\n\t}"
        :: "r"(a), "r"(par) : "memory");
}
DINL void tma2d(uint32_t dst, const void* map, int cx, int cy, uint32_t mbar) {
    asm volatile(
        "cp.async.bulk.tensor.2d.shared::cta.global.tile.mbarrier::complete_tx::bytes "
        "[%0], [%1, {%2, %3}], [%4];"
        :: "r"(dst), "l"(map), "r"(cx), "r"(cy), "r"(mbar) : "memory");
}

// ---- split X (2 float4 per thread for MLP) ----
__global__ void __launch_bounds__(256) split_kernel(
    const float4* __restrict__ src, uint2* __restrict__ dh, uint2* __restrict__ dl, size_t n4)
{
    size_t i0 = (size_t)blockIdx.x * 512u + threadIdx.x;
#pragma unroll
    for (int r = 0; r < 2; r++) {
        size_t i = i0 + (size_t)r * 256u;
        if (i >= n4) break;
        float4 x = src[i];
        __nv_bfloat16 h0 = __float2bfloat16(x.x), h1 = __float2bfloat16(x.y);
        __nv_bfloat16 h2 = __float2bfloat16(x.z), h3 = __float2bfloat16(x.w);
        dh[i] = make_uint2(pack_bf2(h0, h1), pack_bf2(h2, h3));
        dl[i] = make_uint2(
            pack_bf2(__float2bfloat16(x.x - __bfloat162float(h0)),
                     __float2bfloat16(x.y - __bfloat162float(h1))),
            pack_bf2(__float2bfloat16(x.z - __bfloat162float(h2)),
                     __float2bfloat16(x.w - __bfloat162float(h3))));
    }
}

// ---- transpose + split weights ----
__global__ void __launch_bounds__(256) tsplit_kernel(
    const float* __restrict__ src, __nv_bfloat16* __restrict__ dh,
    __nv_bfloat16* __restrict__ dl, int R, int C)
{
    __shared__ float tile[32][33];
    int c0 = blockIdx.x * 32, r0 = blockIdx.y * 32;
    int tx = threadIdx.x, ty = threadIdx.y;
#pragma unroll
    for (int j = 0; j < 32; j += 8)
        tile[ty + j][tx] = src[(size_t)(r0 + ty + j) * C + (c0 + tx)];
    __syncthreads();
#pragma unroll
    for (int j = 0; j < 32; j += 8) {
        float v = tile[tx][ty + j];
        size_t o = (size_t)(c0 + ty + j) * R + (r0 + tx);
        __nv_bfloat16 h = __float2bfloat16(v);
        dh[o] = h;
        dl[o] = __float2bfloat16(v - __bfloat162float(h));
    }
}

// ---- W3 f32 -> fp16 ----
__global__ void __launch_bounds__(256) htrunc_kernel(
    const float4* __restrict__ src, uint2* __restrict__ dst, size_t n4)
{
    size_t i = (size_t)blockIdx.x * 256u + threadIdx.x;
    if (i >= n4) return;
    float4 x = src[i];
    __half2 lo = __floats2half2_rn(x.x, x.y);
    __half2 hi = __floats2half2_rn(x.z, x.w);
    dst[i] = make_uint2(*(uint32_t*)&lo, *(uint32_t*)&hi);
}

// ---- exact top-k threshold + deterministic compaction ----
DINL unsigned fmap(float x) {
    unsigned b = __float_as_uint(x);
    return (b & 0x80000000u) ? ~b : (b | 0x80000000u);
}
__global__ void __launch_bounds__(256) topk_kernel(
    const float* __restrict__ H2, const int* __restrict__ knb,
    float* __restrict__ gv, int* __restrict__ gi, int* __restrict__ gc)
{
    __shared__ int hist[256];
    __shared__ unsigned sh_pref;
    __shared__ int sh_k;
    __shared__ float s_val[NCAP];
    __shared__ int s_idx[NCAP];
    __shared__ int wsum[8];
    __shared__ int s_tot;
    const int row = blockIdx.x, t = threadIdx.x;
    const int lane = t & 31, w = t >> 5;
    const float* rp = H2 + (size_t)row * HID;
    float v[8]; unsigned u[8];
#pragma unroll
    for (int j = 0; j < 8; j++) { v[j] = rp[t + 256 * j]; u[j] = fmap(v[j]); }
    int k = *knb;
    unsigned prefix = 0, mask = 0;
#pragma unroll 1
    for (int by = 3; by >= 0; by--) {
        hist[t] = 0;
        __syncthreads();
#pragma unroll
        for (int j = 0; j < 8; j++)
            if ((u[j] & mask) == prefix)
                atomicAdd(&hist[(u[j] >> (by * 8)) & 255], 1);
        __syncthreads();
        if (t == 0) {
            int cum = 0, d = 255;
            for (; d > 0; d--) { cum += hist[d]; if (cum >= k) break; }
            if (cum < k) cum += hist[0];
            sh_pref = prefix | ((unsigned)d << (by * 8));
            sh_k = k - (cum - hist[d]);
        }
        __syncthreads();
        prefix = sh_pref; k = sh_k;
        mask |= (0xFFu << (by * 8));
        __syncthreads();
    }
    const unsigned th = prefix;

    int n = 0;
    bool act[8];
#pragma unroll
    for (int j = 0; j < 8; j++) { act[j] = (u[j] >= th); n += act[j] ? 1 : 0; }
    int incl = n;
#pragma unroll
    for (int o = 1; o < 32; o <<= 1) {
        int y = __shfl_up_sync(0xFFFFFFFFu, incl, o);
        if (lane >= o) incl += y;
    }
    if (lane == 31) wsum[w] = incl;
    __syncthreads();
    if (t == 0) {
        int a = 0;
#pragma unroll
        for (int i = 0; i < 8; i++) { int b = wsum[i]; wsum[i] = a; a += b; }
        s_tot = (a > NCAP) ? NCAP : a;
    }
    __syncthreads();
    int pos = wsum[w] + incl - n;
#pragma unroll
    for (int j = 0; j < 8; j++) {
        if (act[j] && pos < NCAP) { s_val[pos] = v[j]; s_idx[pos] = t + 256 * j; pos++; }
    }
    __syncthreads();
    int tot = s_tot;
    if (t < NCAP) {
        gv[(size_t)row * NCAP + t] = (t < tot) ? s_val[t] : 0.0f;
        gi[(size_t)row * NCAP + t] = (t < tot) ? s_idx[t] : 0;
    }
    if (t == 0) gc[row] = tot;
}

// ---- sparse layer 3 (fp16 W3, one uint4 load per k) ----
__global__ void __launch_bounds__(256) sparse_out_kernel(
    const float* __restrict__ gv, const int* __restrict__ gi, const int* __restrict__ gc,
    const __half* __restrict__ W3, const float* __restrict__ b3, float* __restrict__ out)
{
    __shared__ float sv[NCAP];
    __shared__ int si[NCAP];
    const int row = blockIdx.x, ch = blockIdx.y, t = threadIdx.x;
    if (t < NCAP) {
        sv[t] = gv[(size_t)row * NCAP + t];
        si[t] = gi[(size_t)row * NCAP + t];
    }
    __syncthreads();
    const int cnt = gc[row];
    const int c0 = ch * CCH + 8 * t;

    float a[8] = {0, 0, 0, 0, 0, 0, 0, 0};
#pragma unroll 2
    for (int k = 0; k < cnt; k++) {
        float vv = sv[k];
        uint4 q = *(const uint4*)(W3 + (size_t)si[k] * D_IN + c0);
        float2 p;
        p = __half22float2(*(__half2*)&q.x); a[0] += vv * p.x; a[1] += vv * p.y;
        p = __half22float2(*(__half2*)&q.y); a[2] += vv * p.x; a[3] += vv * p.y;
        p = __half22float2(*(__half2*)&q.z); a[4] += vv * p.x; a[5] += vv * p.y;
        p = __half22float2(*(__half2*)&q.w); a[6] += vv * p.x; a[7] += vv * p.y;
    }
    float4 b0 = *(const float4*)(b3 + c0);
    float4 b1 = *(const float4*)(b3 + c0 + 4);
    float4 o0, o1;
    o0.x = 1.0f / (1.0f + __expf(-(a[0] + b0.x)));
    o0.y = 1.0f / (1.0f + __expf(-(a[1] + b0.y)));
    o0.z = 1.0f / (1.0f + __expf(-(a[2] + b0.z)));
    o0.w = 1.0f / (1.0f + __expf(-(a[3] + b0.w)));
    o1.x = 1.0f / (1.0f + __expf(-(a[4] + b1.x)));
    o1.y = 1.0f / (1.0f + __expf(-(a[5] + b1.y)));
    o1.z = 1.0f / (1.0f + __expf(-(a[6] + b1.z)));
    o1.w = 1.0f / (1.0f + __expf(-(a[7] + b1.w)));
    float* op = out + (size_t)row * D_IN + c0;
    *(float4*)(op)     = o0;
    *(float4*)(op + 4) = o1;
}

// ---- shared epilogue ----
template <int EPI>
DINL void gemm_epilogue(float c[2][8][4], int mtile, int ntile, int m0, int n0,
                        int g, int t, const float* bias, float* out_f,
                        __nv_bfloat16* out_h, __nv_bfloat16* out_l, int ldo)
{
#pragma unroll
    for (int i = 0; i < 2; i++) {
        int r0 = mtile * 128 + m0 + i * 16 + g;
#pragma unroll
        for (int j = 0; j < 8; j++) {
            int col = ntile * 128 + n0 + j * 8 + 2 * t;
            float2 bb = *(const float2*)&bias[col];
            float v0 = c[i][j][0] + bb.x, v1 = c[i][j][1] + bb.y;
            float v2 = c[i][j][2] + bb.x, v3 = c[i][j][3] + bb.y;
            if (EPI == 0) {
                v0 = fmaxf(v0, 0.0f); v1 = fmaxf(v1, 0.0f);
                v2 = fmaxf(v2, 0.0f); v3 = fmaxf(v3, 0.0f);
                __nv_bfloat16 h0 = __float2bfloat16(v0), h1 = __float2bfloat16(v1);
                __nv_bfloat16 h2 = __float2bfloat16(v2), h3 = __float2bfloat16(v3);
                *(uint32_t*)&out_h[(size_t)r0 * ldo + col]       = pack_bf2(h0, h1);
                *(uint32_t*)&out_h[(size_t)(r0 + 8) * ldo + col] = pack_bf2(h2, h3);
                *(uint32_t*)&out_l[(size_t)r0 * ldo + col] =
                    pack_bf2(__float2bfloat16(v0 - __bfloat162float(h0)),
                             __float2bfloat16(v1 - __bfloat162float(h1)));
                *(uint32_t*)&out_l[(size_t)(r0 + 8) * ldo + col] =
                    pack_bf2(__float2bfloat16(v2 - __bfloat162float(h2)),
                             __float2bfloat16(v3 - __bfloat162float(h3)));
            } else {
                *(float2*)&out_f[(size_t)r0 * ldo + col]       = make_float2(v0, v1);
                *(float2*)&out_f[(size_t)(r0 + 8) * ldo + col] = make_float2(v2, v3);
            }
        }
    }
}

// ---- TMA split-bf16 GEMM (early empty-arrive after final LDSM of each stage) ----
template <int EPI>
__global__ void __launch_bounds__(256, 1) gemm_tma(
    const __grid_constant__ CUtensorMap mAh, const __grid_constant__ CUtensorMap mAl,
    const __grid_constant__ CUtensorMap mBh, const __grid_constant__ CUtensorMap mBl,
    const float* __restrict__ bias, int K,
    float* __restrict__ out_f,
    __nv_bfloat16* __restrict__ out_h, __nv_bfloat16* __restrict__ out_l, int ldo)
{
    extern __shared__ __align__(16) char smem[];
    __shared__ __align__(8) uint64_t mbars[6];   // full[0..2], empty[3..5]
    const int tid = threadIdx.x;
    const int wid = tid >> 5, lane = tid & 31;
    const int g = lane >> 2, t = lane & 3;
    const int m4 = lane >> 3, r8 = lane & 7;
    const int m0 = (wid & 3) * 32, n0 = (wid >> 2) * 64;
    const int mtile = blockIdx.y, ntile = blockIdx.x;
    const int KT = K / 64;
    const uint32_t base = (smem_u32(smem) + 1023u) & ~1023u;
    const uint32_t mb = smem_u32(mbars);

    float c[2][8][4];
#pragma unroll
    for (int i = 0; i < 2; i++)
#pragma unroll
        for (int j = 0; j < 8; j++)
#pragma unroll
            for (int q = 0; q < 4; q++) c[i][j][q] = 0.0f;

    uint32_t baA[2], xmA[2], baB[4], xmB[4];
    const uint32_t selA = (uint32_t)((m4 >> 1) << 4);
    const uint32_t selB = (uint32_t)((m4 & 1) << 4);
#pragma unroll
    for (int i = 0; i < 2; i++) {
        uint32_t r = (uint32_t)(m0 + i * 16 + ((m4 & 1) << 3) + r8);
        baA[i] = r * 128u;
        xmA[i] = (r & 7u) << 4;
    }
#pragma unroll
    for (int q = 0; q < 4; q++) {
        uint32_t r = (uint32_t)(n0 + (2 * q + (m4 >> 1)) * 8 + r8);
        baB[q] = r * 128u;
        xmB[q] = (r & 7u) << 4;
    }

    if (tid == 0) {
#pragma unroll
        for (int s = 0; s < 3; s++) { mbar_init(mb + 8 * s, 1); mbar_init(mb + 24 + 8 * s, 8); }
    }
    __syncthreads();

    auto issue = [&](int kt) {
        int buf = kt % 3;
        uint32_t sb = base + (uint32_t)buf * TSTAGE;
        uint32_t fb = mb + 8 * buf;
        mbar_expect(fb, TSTAGE);
        tma2d(sb,             &mAh, kt * 64, mtile * 128, fb);
        tma2d(sb + TTILE,     &mAl, kt * 64, mtile * 128, fb);
        tma2d(sb + 2 * TTILE, &mBh, kt * 64, ntile * 128, fb);
        tma2d(sb + 3 * TTILE, &mBl, kt * 64, ntile * 128, fb);
    };

    if (tid == 0) {
        int np = KT < 3 ? KT : 3;
        for (int p = 0; p < np; p++) issue(p);
    }

#pragma unroll 1
    for (int kt = 0; kt < KT; kt++) {
        const int buf = kt % 3;
        const uint32_t ph = (uint32_t)((kt / 3) & 1);
        mbar_wait(mb + 8 * buf, ph);

        const uint32_t sA = base + (uint32_t)buf * TSTAGE;
        const uint32_t sAl = sA + TTILE, sBh = sA + 2 * TTILE, sBl = sA + 3 * TTILE;

#pragma unroll
        for (int kk = 0; kk < 4; kk++) {
            const uint32_t cbA = (uint32_t)(kk * 32) + selA;
            const uint32_t cbB = (uint32_t)(kk * 32) + selB;
            uint32_t ah[2][4], al[2][4], bh[8][2], bl[8][2];
#pragma unroll
            for (int i = 0; i < 2; i++) {
                uint32_t o = baA[i] + (cbA ^ xmA[i]);
                ldsm4(ah[i][0], ah[i][1], ah[i][2], ah[i][3], sA + o);
                ldsm4(al[i][0], al[i][1], al[i][2], al[i][3], sAl + o);
            }
#pragma unroll
            for (int q = 0; q < 4; q++) {
                uint32_t o = baB[q] + (cbB ^ xmB[q]);
                ldsm4(bh[2 * q][0], bh[2 * q][1], bh[2 * q + 1][0], bh[2 * q + 1][1], sBh + o);
                ldsm4(bl[2 * q][0], bl[2 * q][1], bl[2 * q + 1][0], bl[2 * q + 1][1], sBl + o);
            }
            if (kk == 3 && elect_one()) mbar_arrive(mb + 24 + 8 * buf);
#pragma unroll
            for (int i = 0; i < 2; i++)
#pragma unroll
                for (int j = 0; j < 8; j++) {
                    mma_bf16(c[i][j], ah[i][0], ah[i][1], ah[i][2], ah[i][3], bh[j][0], bh[j][1]);
                    mma_bf16(c[i][j], ah[i][0], ah[i][1], ah[i][2], ah[i][3], bl[j][0], bl[j][1]);
                    mma_bf16(c[i][j], al[i][0], al[i][1], al[i][2], al[i][3], bh[j][0], bh[j][1]);
                }
        }

        if (tid == 0 && kt + 3 < KT) {
            mbar_wait(mb + 24 + 8 * buf, ph);
            issue(kt + 3);
        }
    }

    gemm_epilogue<EPI>(c, mtile, ntile, m0, n0, g, t, bias, out_f, out_h, out_l, ldo);
}

// ---- fallback cp.async split-bf16 GEMM ----
template <int EPI>
__global__ void __launch_bounds__(256, 1) gemm_kernel(
    const __nv_bfloat16* __restrict__ Ah, const __nv_bfloat16* __restrict__ Al,
    const __nv_bfloat16* __restrict__ Bh, const __nv_bfloat16* __restrict__ Bl,
    const float* __restrict__ bias, int K,
    float* __restrict__ out_f,
    __nv_bfloat16* __restrict__ out_h, __nv_bfloat16* __restrict__ out_l, int ldo)
{
    extern __shared__ __align__(16) char smem[];
    const int tid = threadIdx.x;
    const int wid = tid >> 5, lane = tid & 31;
    const int g = lane >> 2, t = lane & 3;
    const int m4 = lane >> 3, r8 = lane & 7;
    const int m0 = (wid & 3) * 32, n0 = (wid >> 2) * 64;
    const int mtile = blockIdx.y, ntile = blockIdx.x;
    const int KT = K / TKT;
    const __nv_bfloat16* gbase[4] = { Ah, Al, Bh, Bl };

    float c[2][8][4];
#pragma unroll
    for (int i = 0; i < 2; i++)
#pragma unroll
        for (int j = 0; j < 8; j++)
#pragma unroll
            for (int q = 0; q < 4; q++) c[i][j][q] = 0.0f;

    uint32_t offA[2], offB[4];
#pragma unroll
    for (int i = 0; i < 2; i++)
        offA[i] = (uint32_t)(((m0 + i * 16 + ((m4 & 1) << 3) + r8) * SROW
                              + ((m4 >> 1) << 3)) * 2);
#pragma unroll
    for (int q = 0; q < 4; q++)
        offB[q] = (uint32_t)(((n0 + (2 * q + (m4 >> 1)) * 8 + r8) * SROW
                              + ((m4 & 1) << 3)) * 2);

    const uint32_t sb0 = smem_u32(smem);

    auto load_stage = [&](int kt, int buf) {
        char* sb = smem + buf * STAGE_BYTES;
#pragma unroll
        for (int i = 0; i < 16; i++) {
            int id = tid + 256 * i;
            int arr = id >> 10;
            int rem = id & 1023;
            int row = rem >> 3, chunk = rem & 7;
            int grow = ((arr < 2) ? mtile : ntile) * 128 + row;
            const char* src = (const char*)(gbase[arr] + (size_t)grow * K + (size_t)kt * TKT)
                              + chunk * 16;
            uint32_t dst = smem_u32(sb + arr * TILE_BYTES + row * (SROW * 2) + chunk * 16);
            cp16(dst, src);
        }
    };

    load_stage(0, 0);
    cp_commit();
    load_stage(1, 1);
    cp_commit();

#pragma unroll 1
    for (int kt = 0; kt < KT; kt++) {
        if (kt + 1 < KT) cp_wait<1>(); else cp_wait<0>();
        __syncthreads();
        if (kt + 2 < KT) { load_stage(kt + 2, (kt + 2) % NSTAGE); cp_commit(); }

        const uint32_t sA = sb0 + (kt % NSTAGE) * STAGE_BYTES;
        const uint32_t sB = sA + 2 * TILE_BYTES;

#pragma unroll
        for (int kk = 0; kk < 4; kk++) {
            const uint32_t kb = (uint32_t)kk * 32;
            uint32_t ah[2][4], al[2][4], bh[8][2], bl[8][2];
#pragma unroll
            for (int i = 0; i < 2; i++) {
                ldsm4(ah[i][0], ah[i][1], ah[i][2], ah[i][3], sA + offA[i] + kb);
                ldsm4(al[i][0], al[i][1], al[i][2], al[i][3], sA + TILE_BYTES + offA[i] + kb);
            }
#pragma unroll
            for (int q = 0; q < 4; q++) {
                ldsm4(bh[2 * q][0], bh[2 * q][1], bh[2 * q + 1][0], bh[2 * q + 1][1],
                      sB + offB[q] + kb);
                ldsm4(bl[2 * q][0], bl[2 * q][1], bl[2 * q + 1][0], bl[2 * q + 1][1],
                      sB + TILE_BYTES + offB[q] + kb);
            }
#pragma unroll
            for (int i = 0; i < 2; i++)
#pragma unroll
                for (int j = 0; j < 8; j++) {
                    mma_bf16(c[i][j], ah[i][0], ah[i][1], ah[i][2], ah[i][3], bh[j][0], bh[j][1]);
                    mma_bf16(c[i][j], ah[i][0], ah[i][1], ah[i][2], ah[i][3], bl[j][0], bl[j][1]);
                    mma_bf16(c[i][j], al[i][0], al[i][1], al[i][2], al[i][3], bh[j][0], bh[j][1]);
                }
        }
        __syncthreads();
    }

    gemm_epilogue<EPI>(c, mtile, ntile, m0, n0, g, t, bias, out_f, out_h, out_l, ldo);
}

// ---- host ----
template <typename T> static T* sym(const void* s) {
    void* p = nullptr;
    cudaGetSymbolAddress(&p, s);
    return (T*)p;
}

typedef CUresult (*EncFn)(CUtensorMap*, CUtensorMapDataType, cuuint32_t, void*,
                          const cuuint64_t*, const cuuint64_t*, const cuuint32_t*,
                          const cuuint32_t*, CUtensorMapInterleave, CUtensorMapSwizzle,
                          CUtensorMapL2promotion, CUtensorMapFloatOOBfill);

static bool enc2d(EncFn enc, CUtensorMap* m, void* ptr, uint64_t K, uint64_t R) {
    cuuint64_t dims[2] = { K, R };
    cuuint64_t strides[1] = { K * 2 };
    cuuint32_t box[2] = { 64, 128 };
    cuuint32_t es[2] = { 1, 1 };
    return enc(m, CU_TENSOR_MAP_DATA_TYPE_BFLOAT16, 2, ptr, dims, strides, box, es,
               CU_TENSOR_MAP_INTERLEAVE_NONE, CU_TENSOR_MAP_SWIZZLE_128B,
               CU_TENSOR_MAP_L2_PROMOTION_L2_128B,
               CU_TENSOR_MAP_FLOAT_OOB_FILL_NONE) == CUDA_SUCCESS;
}

extern "C" void kernel_launch(void* const* d_in, const int* in_sizes, int n_in,
                              void* d_out, int out_size)
{
    const float* X  = (const float*)d_in[0];
    const float* W1 = (const float*)d_in[1];
    const float* b1 = (const float*)d_in[2];
    const float* W2 = (const float*)d_in[3];
    const float* b2 = (const float*)d_in[4];
    const float* W3 = (const float*)d_in[5];
    const float* b3 = (const float*)d_in[6];
    const int* knb  = (const int*)d_in[7];
    float* out = (float*)d_out;

    __nv_bfloat16* Xh  = sym<__nv_bfloat16>(g_Xh);
    __nv_bfloat16* Xl  = sym<__nv_bfloat16>(g_Xl);
    __nv_bfloat16* W1h = sym<__nv_bfloat16>(g_W1h);
    __nv_bfloat16* W1l = sym<__nv_bfloat16>(g_W1l);
    __nv_bfloat16* W2h = sym<__nv_bfloat16>(g_W2h);
    __nv_bfloat16* W2l = sym<__nv_bfloat16>(g_W2l);
    __half*        W3f = sym<__half>(g_W3f);
    __nv_bfloat16* H1h = sym<__nv_bfloat16>(g_H1h);
    __nv_bfloat16* H1l = sym<__nv_bfloat16>(g_H1l);
    float*         H2  = sym<float>(g_H2);
    float*         gv  = sym<float>(g_sv);
    int*           gi  = sym<int>(g_si);
    int*           gc  = sym<int>(g_sc);

    void* h = dlopen("libcuda.so.1", RTLD_LAZY | RTLD_GLOBAL);
    if (!h) h = dlopen("libcuda.so", RTLD_LAZY | RTLD_GLOBAL);
    EncFn enc = h ? (EncFn)dlsym(h, "cuTensorMapEncodeTiled") : nullptr;
    CUtensorMap mXh, mXl, mW1h, mW1l, mH1h, mH1l, mW2h, mW2l;
    bool tma_ok = (enc != nullptr);
    if (tma_ok) {
        tma_ok = enc2d(enc, &mXh, Xh, D_IN, B_ROWS) && enc2d(enc, &mXl, Xl, D_IN, B_ROWS)
              && enc2d(enc, &mW1h, W1h, D_IN, HID)  && enc2d(enc, &mW1l, W1l, D_IN, HID)
              && enc2d(enc, &mH1h, H1h, HID, B_ROWS) && enc2d(enc, &mH1l, H1l, HID, B_ROWS)
              && enc2d(enc, &mW2h, W2h, HID, HID)   && enc2d(enc, &mW2l, W2l, HID, HID);
    }

    cudaFuncSetAttribute(gemm_tma<0>, cudaFuncAttributeMaxDynamicSharedMemorySize, TSMEM);
    cudaFuncSetAttribute(gemm_tma<1>, cudaFuncAttributeMaxDynamicSharedMemorySize, TSMEM);
    cudaFuncSetAttribute(gemm_kernel<0>, cudaFuncAttributeMaxDynamicSharedMemorySize, SMEM_DYN);
    cudaFuncSetAttribute(gemm_kernel<1>, cudaFuncAttributeMaxDynamicSharedMemorySize, SMEM_DYN);

    // side stream for prep work not needed until G2/sparse_out
    cudaStream_t s2 = 0;
    cudaEvent_t eFork = 0, eJoin = 0;
    bool use_s2 = (cudaStreamCreateWithFlags(&s2, cudaStreamNonBlocking) == cudaSuccess);
    if (use_s2) {
        use_s2 = (cudaEventCreateWithFlags(&eFork, cudaEventDisableTiming) == cudaSuccess)
              && (cudaEventCreateWithFlags(&eJoin, cudaEventDisableTiming) == cudaSuccess);
    }

    size_t n4 = (size_t)B_ROWS * D_IN / 4;
    size_t w34 = (size_t)HID * D_IN / 4;
    dim3 t8(32, 8);

    // main-stream prep needed by G1
    split_kernel<<<(unsigned)((n4 + 511) / 512), 256>>>((const float4*)X, (uint2*)Xh, (uint2*)Xl, n4);
    tsplit_kernel<<<dim3(HID / 32, D_IN / 32), t8>>>(W1, W1h, W1l, D_IN, HID);

    // fork: htrunc (needed by step 6) + tsplit W2 (needed by G2) overlap with G1
    if (use_s2) {
        cudaEventRecord(eFork, 0);
        cudaStreamWaitEvent(s2, eFork, 0);
        htrunc_kernel<<<(unsigned)((w34 + 255) / 256), 256, 0, s2>>>((const float4*)W3, (uint2*)W3f, w34);
        tsplit_kernel<<<dim3(HID / 32, HID / 32), t8, 0, s2>>>(W2, W2h, W2l, HID, HID);
        cudaEventRecord(eJoin, s2);
    } else {
        htrunc_kernel<<<(unsigned)((w34 + 255) / 256), 256>>>((const float4*)W3, (uint2*)W3f, w34);
        tsplit_kernel<<<dim3(HID / 32, HID / 32), t8>>>(W2, W2h, W2l, HID, HID);
    }

    // 3. G1 (needs X split + W1 split only)
    if (tma_ok) {
        gemm_tma<0><<<dim3(HID / 128, B_ROWS / 128), 256, TSMEM>>>(
            mXh, mXl, mW1h, mW1l, b1, D_IN, nullptr, H1h, H1l, HID);
    } else {
        gemm_kernel<0><<<dim3(HID / TNT, B_ROWS / TMT), 256, SMEM_DYN>>>(
            Xh, Xl, W1h, W1l, b1, D_IN, nullptr, H1h, H1l, HID);
    }

    // join before G2 (needs W2; htrunc also joined here, well before sparse_out)
    if (use_s2) cudaStreamWaitEvent(0, eJoin, 0);

    // 4. G2
    if (tma_ok) {
        gemm_tma<1><<<dim3(HID / 128, B_ROWS / 128), 256, TSMEM>>>(
            mH1h, mH1l, mW2h, mW2l, b2, HID, H2, nullptr, nullptr, HID);
    } else {
        gemm_kernel<1><<<dim3(HID / TNT, B_ROWS / TMT), 256, SMEM_DYN>>>(
            H1h, H1l, W2h, W2l, b2, HID, H2, nullptr, nullptr, HID);
    }

    // 5. top-k -> compacted (val, idx, cnt)
    topk_kernel<<<B_ROWS, 256>>>(H2, knb, gv, gi, gc);

    // 6. sparse layer 3 + sigmoid (fp16 W3)
    sparse_out_kernel<<<dim3(B_ROWS, D_IN / CCH), 256>>>(gv, gi, gc, W3f, b3, out);

    if (use_s2) {
        cudaEventDestroy(eFork);
        cudaEventDestroy(eJoin);
    }
    if (s2) cudaStreamDestroy(s2);

    (void)in_sizes; (void)n_in; (void)out_size;
}